// round 1
// baseline (speedup 1.0000x reference)
#include <cuda_runtime.h>
#include <math.h>

#define NMAX 50000
#define EMAX 800000
#define HD   128

// Scratch (device globals — no allocation allowed)
__device__ __align__(16) float g_deg[NMAX];
__device__ __align__(16) float g_dinv[NMAX];
__device__ __align__(16) float g_enorm[EMAX];
__device__ __align__(16) float g_h[(size_t)NMAX * HD];    // GEMM output
__device__ __align__(16) float g_agg[(size_t)NMAX * HD];  // aggregation / layer output

// ---------------------------------------------------------------------------
// vectorized global reduction (no return) — sm_90+
__device__ __forceinline__ void red_add4(float* addr, float a, float b, float c, float d) {
    asm volatile("red.global.add.v4.f32 [%0], {%1, %2, %3, %4};"
                 :: "l"(addr), "f"(a), "f"(b), "f"(c), "f"(d) : "memory");
}

// ---------------------------------------------------------------------------
__global__ void k_deg_init(float* __restrict__ deg, int n) {
    int i = blockIdx.x * blockDim.x + threadIdx.x;
    if (i < n) deg[i] = 1.0f;  // self-loop weight
}

__global__ void k_deg_scatter(const int* __restrict__ dst, const float* __restrict__ ew,
                              float* __restrict__ deg, int E) {
    int e = blockIdx.x * blockDim.x + threadIdx.x;
    if (e < E) atomicAdd(&deg[dst[e]], ew[e]);
}

__global__ void k_dinv(const float* __restrict__ deg, float* __restrict__ dinv, int n) {
    int i = blockIdx.x * blockDim.x + threadIdx.x;
    if (i < n) {
        float d = deg[i];
        dinv[i] = d > 0.0f ? rsqrtf(d) : 0.0f;
    }
}

__global__ void k_enorm(const int* __restrict__ src, const int* __restrict__ dst,
                        const float* __restrict__ ew, const float* __restrict__ dinv,
                        float* __restrict__ enorm, int E) {
    int e = blockIdx.x * blockDim.x + threadIdx.x;
    if (e < E) enorm[e] = dinv[src[e]] * ew[e] * dinv[dst[e]];
}

// ---------------------------------------------------------------------------
// C[M,128] = A[M,K] @ B[K,128], row-major. BM=64, BN=128, BK=16, 256 threads,
// 4x8 register tile per thread.
__global__ void k_gemm(const float* __restrict__ A, const float* __restrict__ B,
                       float* __restrict__ C, int M, int K) {
    __shared__ float As[16][68];    // [k][m], padded
    __shared__ float Bs[16][128];   // [k][n]
    const int tid = threadIdx.x;
    const int ty = tid >> 4;        // 0..15 -> row group
    const int tx = tid & 15;        // 0..15 -> col group
    const int m0 = blockIdx.x * 64;

    float acc[4][8];
#pragma unroll
    for (int i = 0; i < 4; i++)
#pragma unroll
        for (int j = 0; j < 8; j++) acc[i][j] = 0.0f;

    const int arow = tid >> 2;          // 0..63
    const int akc  = (tid & 3) << 2;    // 0,4,8,12

    for (int k0 = 0; k0 < K; k0 += 16) {
        // load A tile 64x16 (one float4 per thread), transpose into As
        float4 av = make_float4(0.f, 0.f, 0.f, 0.f);
        int grow = m0 + arow;
        if (grow < M)
            av = *(const float4*)(A + (size_t)grow * K + k0 + akc);
        As[akc + 0][arow] = av.x;
        As[akc + 1][arow] = av.y;
        As[akc + 2][arow] = av.z;
        As[akc + 3][arow] = av.w;
        // load B tile 16x128 (two float4 per thread)
#pragma unroll
        for (int i = 0; i < 2; i++) {
            int idx  = tid + i * 256;       // 0..511 float4 slots
            int brow = idx >> 5;            // 0..15
            int bcol = (idx & 31) << 2;     // 0..124
            float4 bv = *(const float4*)(B + (size_t)(k0 + brow) * 128 + bcol);
            *(float4*)&Bs[brow][bcol] = bv;
        }
        __syncthreads();
#pragma unroll
        for (int k = 0; k < 16; k++) {
            float a[4], b[8];
#pragma unroll
            for (int i = 0; i < 4; i++) a[i] = As[k][ty * 4 + i];
#pragma unroll
            for (int j = 0; j < 8; j++) b[j] = Bs[k][tx * 8 + j];
#pragma unroll
            for (int i = 0; i < 4; i++)
#pragma unroll
                for (int j = 0; j < 8; j++)
                    acc[i][j] = fmaf(a[i], b[j], acc[i][j]);
        }
        __syncthreads();
    }
#pragma unroll
    for (int i = 0; i < 4; i++) {
        int grow = m0 + ty * 4 + i;
        if (grow < M) {
            float* cp = C + (size_t)grow * 128 + tx * 8;
            *(float4*)cp       = make_float4(acc[i][0], acc[i][1], acc[i][2], acc[i][3]);
            *(float4*)(cp + 4) = make_float4(acc[i][4], acc[i][5], acc[i][6], acc[i][7]);
        }
    }
}

// ---------------------------------------------------------------------------
// agg[i,:] = h[i,:] * dinv[i]^2   (self-loop term)
__global__ void k_self(const float* __restrict__ h, const float* __restrict__ dinv,
                       float* __restrict__ agg, int n) {
    int idx = blockIdx.x * blockDim.x + threadIdx.x;   // float4 index
    if (idx < n * (HD / 4)) {
        int node = idx >> 5;
        float s = dinv[node];
        s = s * s;
        float4 v = ((const float4*)h)[idx];
        v.x *= s; v.y *= s; v.z *= s; v.w *= s;
        ((float4*)agg)[idx] = v;
    }
}

// one warp per edge: agg[dst,:] += h[src,:] * enorm[e]
__global__ void k_edge(const int* __restrict__ src, const int* __restrict__ dst,
                       const float* __restrict__ enorm, const float* __restrict__ h,
                       float* __restrict__ agg, int E) {
    int warp = (blockIdx.x * blockDim.x + threadIdx.x) >> 5;
    int lane = threadIdx.x & 31;
    if (warp >= E) return;
    int s   = __ldg(src + warp);
    int d   = __ldg(dst + warp);
    float w = __ldg(enorm + warp);
    float4 v = *(const float4*)(h + (size_t)s * HD + lane * 4);
    red_add4(agg + (size_t)d * HD + lane * 4, v.x * w, v.y * w, v.z * w, v.w * w);
}

// agg = relu(agg + b), in place
__global__ void k_bias_relu(float* __restrict__ agg, const float* __restrict__ b, int n) {
    int idx = blockIdx.x * blockDim.x + threadIdx.x;   // float4 index
    if (idx < n * (HD / 4)) {
        float4 bb = ((const float4*)b)[idx & 31];
        float4 v  = ((float4*)agg)[idx];
        v.x = fmaxf(v.x + bb.x, 0.0f);
        v.y = fmaxf(v.y + bb.y, 0.0f);
        v.z = fmaxf(v.z + bb.z, 0.0f);
        v.w = fmaxf(v.w + bb.w, 0.0f);
        ((float4*)agg)[idx] = v;
    }
}

// ---------------------------------------------------------------------------
// head: warp per node, logits = h @ fc_w + fc_b, softmax over 10 classes
__global__ void k_head(const float* __restrict__ h, const float* __restrict__ fcw,
                       const float* __restrict__ fcb, float* __restrict__ out, int n) {
    __shared__ float sw[HD * 10];
    __shared__ float sb[10];
    for (int i = threadIdx.x; i < HD * 10; i += blockDim.x) sw[i] = fcw[i];
    if (threadIdx.x < 10) sb[threadIdx.x] = fcb[threadIdx.x];
    __syncthreads();
    int node = (blockIdx.x * blockDim.x + threadIdx.x) >> 5;
    int lane = threadIdx.x & 31;
    if (node >= n) return;
    float4 hv = *(const float4*)(h + (size_t)node * HD + lane * 4);
    int k = lane * 4;
    float part[10];
#pragma unroll
    for (int c = 0; c < 10; c++) {
        part[c] = hv.x * sw[(k + 0) * 10 + c] + hv.y * sw[(k + 1) * 10 + c]
                + hv.z * sw[(k + 2) * 10 + c] + hv.w * sw[(k + 3) * 10 + c];
    }
#pragma unroll
    for (int off = 16; off; off >>= 1)
#pragma unroll
        for (int c = 0; c < 10; c++)
            part[c] += __shfl_xor_sync(0xffffffffu, part[c], off);
    if (lane == 0) {
        float m = -1e30f;
#pragma unroll
        for (int c = 0; c < 10; c++) { part[c] += sb[c]; m = fmaxf(m, part[c]); }
        float s = 0.0f;
#pragma unroll
        for (int c = 0; c < 10; c++) { part[c] = expf(part[c] - m); s += part[c]; }
        float inv = 1.0f / s;
#pragma unroll
        for (int c = 0; c < 10; c++) out[(size_t)node * 10 + c] = part[c] * inv;
    }
}

// ---------------------------------------------------------------------------
extern "C" void kernel_launch(void* const* d_in, const int* in_sizes, int n_in,
                              void* d_out, int out_size) {
    const float* x   = (const float*)d_in[0];
    const int*   ei  = (const int*)d_in[1];
    const float* ew  = (const float*)d_in[2];
    const float* W1  = (const float*)d_in[3];
    const float* b1  = (const float*)d_in[4];
    const float* W2  = (const float*)d_in[5];
    const float* b2  = (const float*)d_in[6];
    const float* W3  = (const float*)d_in[7];
    const float* b3  = (const float*)d_in[8];
    const float* fcw = (const float*)d_in[9];
    const float* fcb = (const float*)d_in[10];
    float* out = (float*)d_out;

    const int H = in_sizes[4];              // 128
    const int F = in_sizes[3] / H;          // 256
    const int N = in_sizes[0] / F;          // 50000
    const int E = in_sizes[2];              // 800000
    (void)H; (void)n_in; (void)out_size;

    const int* src = ei;
    const int* dst = ei + E;

    float* deg;   cudaGetSymbolAddress((void**)&deg,   g_deg);
    float* dinv;  cudaGetSymbolAddress((void**)&dinv,  g_dinv);
    float* enorm; cudaGetSymbolAddress((void**)&enorm, g_enorm);
    float* hbuf;  cudaGetSymbolAddress((void**)&hbuf,  g_h);
    float* agg;   cudaGetSymbolAddress((void**)&agg,   g_agg);

    const int T = 256;
    // norm precompute
    k_deg_init   <<<(N + T - 1) / T, T>>>(deg, N);
    k_deg_scatter<<<(E + T - 1) / T, T>>>(dst, ew, deg, E);
    k_dinv       <<<(N + T - 1) / T, T>>>(deg, dinv, N);
    k_enorm      <<<(E + T - 1) / T, T>>>(src, dst, ew, dinv, enorm, E);

    const int gemm_blocks = (N + 63) / 64;
    const int vec_threads = N * (HD / 4);
    const int vec_blocks  = (vec_threads + T - 1) / T;
    const int edge_blocks = (E * 32 + T - 1) / T;

    // layer 1
    k_gemm     <<<gemm_blocks, 256>>>(x, W1, hbuf, N, F);
    k_self     <<<vec_blocks, T>>>(hbuf, dinv, agg, N);
    k_edge     <<<edge_blocks, T>>>(src, dst, enorm, hbuf, agg, E);
    k_bias_relu<<<vec_blocks, T>>>(agg, b1, N);
    // layer 2
    k_gemm     <<<gemm_blocks, 256>>>(agg, W2, hbuf, N, HD);
    k_self     <<<vec_blocks, T>>>(hbuf, dinv, agg, N);
    k_edge     <<<edge_blocks, T>>>(src, dst, enorm, hbuf, agg, E);
    k_bias_relu<<<vec_blocks, T>>>(agg, b2, N);
    // layer 3
    k_gemm     <<<gemm_blocks, 256>>>(agg, W3, hbuf, N, HD);
    k_self     <<<vec_blocks, T>>>(hbuf, dinv, agg, N);
    k_edge     <<<edge_blocks, T>>>(src, dst, enorm, hbuf, agg, E);
    k_bias_relu<<<vec_blocks, T>>>(agg, b3, N);
    // head
    k_head<<<(N * 32 + T - 1) / T, T>>>(agg, fcw, fcb, out, N);
}

// round 2
// speedup vs baseline: 1.2188x; 1.2188x over previous
#include <cuda_runtime.h>
#include <math.h>

#define NMAX 50000
#define EMAX 800000
#define HD   128

// Scratch (device globals — no allocation allowed)
__device__ __align__(16) float g_deg[NMAX];
__device__ __align__(16) float g_dinv[NMAX];
__device__ __align__(16) int   g_cnt[NMAX];
__device__ __align__(16) int   g_off[NMAX];
__device__ __align__(16) int   g_head[NMAX];
__device__ __align__(16) int   g_csr_src[EMAX];
__device__ __align__(16) float g_csr_nrm[EMAX];
__device__ __align__(16) float g_h[(size_t)NMAX * HD];    // GEMM output
__device__ __align__(16) float g_agg[(size_t)NMAX * HD];  // aggregation / layer output

// ---------------------------------------------------------------------------
__global__ void k_init(float* __restrict__ deg, int* __restrict__ cnt, int n) {
    int i = blockIdx.x * blockDim.x + threadIdx.x;
    if (i < n) { deg[i] = 1.0f; cnt[i] = 0; }   // self-loop weight 1
}

__global__ void k_deg_count(const int* __restrict__ dst, const float* __restrict__ ew,
                            float* __restrict__ deg, int* __restrict__ cnt, int E) {
    int e = blockIdx.x * blockDim.x + threadIdx.x;
    if (e < E) {
        int d = dst[e];
        atomicAdd(&deg[d], ew[e]);
        atomicAdd(&cnt[d], 1);
    }
}

__global__ void k_dinv(const float* __restrict__ deg, float* __restrict__ dinv, int n) {
    int i = blockIdx.x * blockDim.x + threadIdx.x;
    if (i < n) {
        float d = deg[i];
        dinv[i] = d > 0.0f ? rsqrtf(d) : 0.0f;
    }
}

// single-block exclusive scan of cnt -> off (and head copy). n <= 50176.
__global__ void k_scan(const int* __restrict__ cnt, int* __restrict__ off,
                       int* __restrict__ head, int n) {
    __shared__ int ssum[1024];
    int tid = threadIdx.x;
    int chunk = (n + 1023) / 1024;
    int lo = tid * chunk;
    int hi = min(lo + chunk, n);
    int s = 0;
    for (int i = lo; i < hi; i++) s += cnt[i];
    ssum[tid] = s;
    __syncthreads();
    // Hillis-Steele inclusive scan
    for (int d = 1; d < 1024; d <<= 1) {
        int v = (tid >= d) ? ssum[tid - d] : 0;
        __syncthreads();
        ssum[tid] += v;
        __syncthreads();
    }
    int base = tid ? ssum[tid - 1] : 0;
    for (int i = lo; i < hi; i++) {
        off[i] = base; head[i] = base;
        base += cnt[i];
    }
}

// scatter edges into CSR order, computing the normalized edge weight inline
__global__ void k_fill(const int* __restrict__ src, const int* __restrict__ dst,
                       const float* __restrict__ ew, const float* __restrict__ dinv,
                       int* __restrict__ head, int* __restrict__ csr_src,
                       float* __restrict__ csr_nrm, int E) {
    int e = blockIdx.x * blockDim.x + threadIdx.x;
    if (e < E) {
        int s = src[e], d = dst[e];
        int p = atomicAdd(&head[d], 1);
        csr_src[p] = s;
        csr_nrm[p] = dinv[s] * ew[e] * dinv[d];
    }
}

// ---------------------------------------------------------------------------
// C[M,128] = A[M,K] @ B[K,128], row-major. BM=64, BN=128, BK=16, 256 threads,
// 4x8 register tile per thread.
__global__ void k_gemm(const float* __restrict__ A, const float* __restrict__ B,
                       float* __restrict__ C, int M, int K) {
    __shared__ float As[16][68];    // [k][m], padded
    __shared__ float Bs[16][128];   // [k][n]
    const int tid = threadIdx.x;
    const int ty = tid >> 4;        // 0..15 -> row group
    const int tx = tid & 15;        // 0..15 -> col group
    const int m0 = blockIdx.x * 64;

    float acc[4][8];
#pragma unroll
    for (int i = 0; i < 4; i++)
#pragma unroll
        for (int j = 0; j < 8; j++) acc[i][j] = 0.0f;

    const int arow = tid >> 2;          // 0..63
    const int akc  = (tid & 3) << 2;    // 0,4,8,12

    for (int k0 = 0; k0 < K; k0 += 16) {
        float4 av = make_float4(0.f, 0.f, 0.f, 0.f);
        int grow = m0 + arow;
        if (grow < M)
            av = *(const float4*)(A + (size_t)grow * K + k0 + akc);
        As[akc + 0][arow] = av.x;
        As[akc + 1][arow] = av.y;
        As[akc + 2][arow] = av.z;
        As[akc + 3][arow] = av.w;
#pragma unroll
        for (int i = 0; i < 2; i++) {
            int idx  = tid + i * 256;
            int brow = idx >> 5;
            int bcol = (idx & 31) << 2;
            float4 bv = *(const float4*)(B + (size_t)(k0 + brow) * 128 + bcol);
            *(float4*)&Bs[brow][bcol] = bv;
        }
        __syncthreads();
#pragma unroll
        for (int k = 0; k < 16; k++) {
            float a[4], b[8];
#pragma unroll
            for (int i = 0; i < 4; i++) a[i] = As[k][ty * 4 + i];
#pragma unroll
            for (int j = 0; j < 8; j++) b[j] = Bs[k][tx * 8 + j];
#pragma unroll
            for (int i = 0; i < 4; i++)
#pragma unroll
                for (int j = 0; j < 8; j++)
                    acc[i][j] = fmaf(a[i], b[j], acc[i][j]);
        }
        __syncthreads();
    }
#pragma unroll
    for (int i = 0; i < 4; i++) {
        int grow = m0 + ty * 4 + i;
        if (grow < M) {
            float* cp = C + (size_t)grow * 128 + tx * 8;
            *(float4*)cp       = make_float4(acc[i][0], acc[i][1], acc[i][2], acc[i][3]);
            *(float4*)(cp + 4) = make_float4(acc[i][4], acc[i][5], acc[i][6], acc[i][7]);
        }
    }
}

// ---------------------------------------------------------------------------
// Fused per-node aggregation: one warp per dst node.
// out[i,:] = relu( dinv[i]^2 * h[i,:] + sum_j nrm_j * h[src_j,:] + bias )
__global__ void k_agg(const float* __restrict__ h, const int* __restrict__ off,
                      const int* __restrict__ cnt, const int* __restrict__ csr_src,
                      const float* __restrict__ csr_nrm, const float* __restrict__ dinv,
                      const float* __restrict__ bias, float* __restrict__ outp, int n) {
    int node = blockIdx.x * (blockDim.x >> 5) + (threadIdx.x >> 5);
    int lane = threadIdx.x & 31;
    if (node >= n) return;

    float s = dinv[node];
    s = s * s;
    float4 acc = *(const float4*)(h + (size_t)node * HD + lane * 4);
    acc.x *= s; acc.y *= s; acc.z *= s; acc.w *= s;

    const int m    = cnt[node];
    const int base = off[node];
    int j = 0;
    for (; j + 4 <= m; j += 4) {
        int s0 = __ldg(csr_src + base + j + 0);
        int s1 = __ldg(csr_src + base + j + 1);
        int s2 = __ldg(csr_src + base + j + 2);
        int s3 = __ldg(csr_src + base + j + 3);
        float w0 = __ldg(csr_nrm + base + j + 0);
        float w1 = __ldg(csr_nrm + base + j + 1);
        float w2 = __ldg(csr_nrm + base + j + 2);
        float w3 = __ldg(csr_nrm + base + j + 3);
        float4 v0 = *(const float4*)(h + (size_t)s0 * HD + lane * 4);
        float4 v1 = *(const float4*)(h + (size_t)s1 * HD + lane * 4);
        float4 v2 = *(const float4*)(h + (size_t)s2 * HD + lane * 4);
        float4 v3 = *(const float4*)(h + (size_t)s3 * HD + lane * 4);
        acc.x = fmaf(w0, v0.x, acc.x); acc.y = fmaf(w0, v0.y, acc.y);
        acc.z = fmaf(w0, v0.z, acc.z); acc.w = fmaf(w0, v0.w, acc.w);
        acc.x = fmaf(w1, v1.x, acc.x); acc.y = fmaf(w1, v1.y, acc.y);
        acc.z = fmaf(w1, v1.z, acc.z); acc.w = fmaf(w1, v1.w, acc.w);
        acc.x = fmaf(w2, v2.x, acc.x); acc.y = fmaf(w2, v2.y, acc.y);
        acc.z = fmaf(w2, v2.z, acc.z); acc.w = fmaf(w2, v2.w, acc.w);
        acc.x = fmaf(w3, v3.x, acc.x); acc.y = fmaf(w3, v3.y, acc.y);
        acc.z = fmaf(w3, v3.z, acc.z); acc.w = fmaf(w3, v3.w, acc.w);
    }
    for (; j < m; j++) {
        int sj = __ldg(csr_src + base + j);
        float wj = __ldg(csr_nrm + base + j);
        float4 v = *(const float4*)(h + (size_t)sj * HD + lane * 4);
        acc.x = fmaf(wj, v.x, acc.x); acc.y = fmaf(wj, v.y, acc.y);
        acc.z = fmaf(wj, v.z, acc.z); acc.w = fmaf(wj, v.w, acc.w);
    }

    float4 bb = ((const float4*)bias)[lane];
    acc.x = fmaxf(acc.x + bb.x, 0.0f);
    acc.y = fmaxf(acc.y + bb.y, 0.0f);
    acc.z = fmaxf(acc.z + bb.z, 0.0f);
    acc.w = fmaxf(acc.w + bb.w, 0.0f);
    *(float4*)(outp + (size_t)node * HD + lane * 4) = acc;
}

// ---------------------------------------------------------------------------
// head: warp per node, logits = h @ fc_w + fc_b, softmax over 10 classes
__global__ void k_head(const float* __restrict__ h, const float* __restrict__ fcw,
                       const float* __restrict__ fcb, float* __restrict__ out, int n) {
    __shared__ float sw[HD * 10];
    __shared__ float sb[10];
    for (int i = threadIdx.x; i < HD * 10; i += blockDim.x) sw[i] = fcw[i];
    if (threadIdx.x < 10) sb[threadIdx.x] = fcb[threadIdx.x];
    __syncthreads();
    int node = (blockIdx.x * blockDim.x + threadIdx.x) >> 5;
    int lane = threadIdx.x & 31;
    if (node >= n) return;
    float4 hv = *(const float4*)(h + (size_t)node * HD + lane * 4);
    int k = lane * 4;
    float part[10];
#pragma unroll
    for (int c = 0; c < 10; c++) {
        part[c] = hv.x * sw[(k + 0) * 10 + c] + hv.y * sw[(k + 1) * 10 + c]
                + hv.z * sw[(k + 2) * 10 + c] + hv.w * sw[(k + 3) * 10 + c];
    }
#pragma unroll
    for (int off = 16; off; off >>= 1)
#pragma unroll
        for (int c = 0; c < 10; c++)
            part[c] += __shfl_xor_sync(0xffffffffu, part[c], off);
    if (lane == 0) {
        float m = -1e30f;
#pragma unroll
        for (int c = 0; c < 10; c++) { part[c] += sb[c]; m = fmaxf(m, part[c]); }
        float s = 0.0f;
#pragma unroll
        for (int c = 0; c < 10; c++) { part[c] = expf(part[c] - m); s += part[c]; }
        float inv = 1.0f / s;
#pragma unroll
        for (int c = 0; c < 10; c++) out[(size_t)node * 10 + c] = part[c] * inv;
    }
}

// ---------------------------------------------------------------------------
extern "C" void kernel_launch(void* const* d_in, const int* in_sizes, int n_in,
                              void* d_out, int out_size) {
    const float* x   = (const float*)d_in[0];
    const int*   ei  = (const int*)d_in[1];
    const float* ew  = (const float*)d_in[2];
    const float* W1  = (const float*)d_in[3];
    const float* b1  = (const float*)d_in[4];
    const float* W2  = (const float*)d_in[5];
    const float* b2  = (const float*)d_in[6];
    const float* W3  = (const float*)d_in[7];
    const float* b3  = (const float*)d_in[8];
    const float* fcw = (const float*)d_in[9];
    const float* fcb = (const float*)d_in[10];
    float* out = (float*)d_out;

    const int H = in_sizes[4];              // 128
    const int F = in_sizes[3] / H;          // 256
    const int N = in_sizes[0] / F;          // 50000
    const int E = in_sizes[2];              // 800000
    (void)n_in; (void)out_size;

    const int* src = ei;
    const int* dst = ei + E;

    float* deg;     cudaGetSymbolAddress((void**)&deg,     g_deg);
    float* dinv;    cudaGetSymbolAddress((void**)&dinv,    g_dinv);
    int*   cnt;     cudaGetSymbolAddress((void**)&cnt,     g_cnt);
    int*   off;     cudaGetSymbolAddress((void**)&off,     g_off);
    int*   head;    cudaGetSymbolAddress((void**)&head,    g_head);
    int*   csrs;    cudaGetSymbolAddress((void**)&csrs,    g_csr_src);
    float* csrn;    cudaGetSymbolAddress((void**)&csrn,    g_csr_nrm);
    float* hbuf;    cudaGetSymbolAddress((void**)&hbuf,    g_h);
    float* agg;     cudaGetSymbolAddress((void**)&agg,     g_agg);

    const int T = 256;
    // norm + CSR precompute
    k_init     <<<(N + T - 1) / T, T>>>(deg, cnt, N);
    k_deg_count<<<(E + T - 1) / T, T>>>(dst, ew, deg, cnt, E);
    k_dinv     <<<(N + T - 1) / T, T>>>(deg, dinv, N);
    k_scan     <<<1, 1024>>>(cnt, off, head, N);
    k_fill     <<<(E + T - 1) / T, T>>>(src, dst, ew, dinv, head, csrs, csrn, E);

    const int gemm_blocks = (N + 63) / 64;
    const int agg_blocks  = (N + 7) / 8;     // 8 warps per block

    // layer 1
    k_gemm<<<gemm_blocks, 256>>>(x, W1, hbuf, N, F);
    k_agg <<<agg_blocks, 256>>>(hbuf, off, cnt, csrs, csrn, dinv, b1, agg, N);
    // layer 2
    k_gemm<<<gemm_blocks, 256>>>(agg, W2, hbuf, N, HD);
    k_agg <<<agg_blocks, 256>>>(hbuf, off, cnt, csrs, csrn, dinv, b2, agg, N);
    // layer 3
    k_gemm<<<gemm_blocks, 256>>>(agg, W3, hbuf, N, HD);
    k_agg <<<agg_blocks, 256>>>(hbuf, off, cnt, csrs, csrn, dinv, b3, agg, N);
    // head
    k_head<<<(N * 32 + T - 1) / T, T>>>(agg, fcw, fcb, out, N);
}

// round 3
// speedup vs baseline: 1.2944x; 1.0621x over previous
#include <cuda_runtime.h>
#include <mma.h>
#include <math.h>

using namespace nvcuda;

#define NMAX 50000
#define NPAD 50048          // multiple of 64 for unguarded wmma stores
#define EMAX 800000
#define HD   128

// Scratch (device globals — no allocation allowed)
__device__ __align__(16) float g_deg[NMAX];
__device__ __align__(16) float g_dinv[NMAX];
__device__ __align__(16) int   g_cnt[NMAX];
__device__ __align__(16) int   g_off[NMAX];
__device__ __align__(16) int   g_head[NMAX];
__device__ __align__(16) int   g_bsum[256];
__device__ __align__(16) int   g_csr_src[EMAX];
__device__ __align__(16) float g_csr_nrm[EMAX];
__device__ __align__(16) float g_h[(size_t)NPAD * HD];    // GEMM output
__device__ __align__(16) float g_agg[(size_t)NPAD * HD];  // aggregation / layer output

// ---------------------------------------------------------------------------
__global__ void k_init(float* __restrict__ deg, int* __restrict__ cnt, int n) {
    int i = blockIdx.x * blockDim.x + threadIdx.x;
    if (i < n) { deg[i] = 1.0f; cnt[i] = 0; }   // self-loop weight 1
}

__global__ void k_deg_count(const int* __restrict__ dst, const float* __restrict__ ew,
                            float* __restrict__ deg, int* __restrict__ cnt, int E) {
    int e = blockIdx.x * blockDim.x + threadIdx.x;
    if (e < E) {
        int d = dst[e];
        atomicAdd(&deg[d], ew[e]);
        atomicAdd(&cnt[d], 1);
    }
}

__global__ void k_dinv(const float* __restrict__ deg, float* __restrict__ dinv, int n) {
    int i = blockIdx.x * blockDim.x + threadIdx.x;
    if (i < n) {
        float d = deg[i];
        dinv[i] = d > 0.0f ? rsqrtf(d) : 0.0f;
    }
}

// --- parallel exclusive scan of cnt -> off (3 small kernels) ---------------
__global__ void k_scan1(const int* __restrict__ cnt, int* __restrict__ off,
                        int* __restrict__ bsum, int n) {
    __shared__ int s[256];
    int i = blockIdx.x * 256 + threadIdx.x;
    int v = (i < n) ? cnt[i] : 0;
    s[threadIdx.x] = v;
    __syncthreads();
    for (int d = 1; d < 256; d <<= 1) {
        int t = (threadIdx.x >= d) ? s[threadIdx.x - d] : 0;
        __syncthreads();
        s[threadIdx.x] += t;
        __syncthreads();
    }
    if (i < n) off[i] = s[threadIdx.x] - v;     // exclusive within block
    if (threadIdx.x == 255) bsum[blockIdx.x] = s[255];
}

__global__ void k_scan2(int* __restrict__ bsum, int nb) {
    __shared__ int s[256];
    int t = threadIdx.x;
    int v = (t < nb) ? bsum[t] : 0;
    s[t] = v;
    __syncthreads();
    for (int d = 1; d < 256; d <<= 1) {
        int u = (t >= d) ? s[t - d] : 0;
        __syncthreads();
        s[t] += u;
        __syncthreads();
    }
    if (t < nb) bsum[t] = s[t] - v;             // exclusive block base
}

__global__ void k_scan3(const int* __restrict__ bsum, int* __restrict__ off,
                        int* __restrict__ head, int n) {
    int i = blockIdx.x * 256 + threadIdx.x;
    if (i < n) {
        int o = off[i] + bsum[blockIdx.x];
        off[i] = o;
        head[i] = o;
    }
}

// scatter edges into CSR order, computing the normalized edge weight inline
__global__ void k_fill(const int* __restrict__ src, const int* __restrict__ dst,
                       const float* __restrict__ ew, const float* __restrict__ dinv,
                       int* __restrict__ head, int* __restrict__ csr_src,
                       float* __restrict__ csr_nrm, int E) {
    int e = blockIdx.x * blockDim.x + threadIdx.x;
    if (e < E) {
        int s = src[e], d = dst[e];
        int p = atomicAdd(&head[d], 1);
        csr_src[p] = s;
        csr_nrm[p] = dinv[s] * ew[e] * dinv[d];
    }
}

// ---------------------------------------------------------------------------
// Tensor-core GEMM: C[M,128] = A[M,K] @ B[K,128] with 3xTF32 compensation.
// BM=64, BN=128, BK=16, 256 threads (8 warps, 2x4 warp grid, 32x32 per warp).
__global__ void k_gemm_tc(const float* __restrict__ A, const float* __restrict__ B,
                          float* __restrict__ C, int M, int K) {
    __shared__ float As_hi[64][20];
    __shared__ float As_lo[64][20];
    __shared__ float Bs_hi[16][136];
    __shared__ float Bs_lo[16][136];

    const int tid = threadIdx.x;
    const int wid = tid >> 5;
    const int wm  = wid >> 2;      // 0..1
    const int wn  = wid & 3;       // 0..3
    const int m0  = blockIdx.x * 64;

    wmma::fragment<wmma::accumulator, 16, 16, 8, float> acc[2][2];
#pragma unroll
    for (int i = 0; i < 2; i++)
#pragma unroll
        for (int j = 0; j < 2; j++) wmma::fill_fragment(acc[i][j], 0.0f);

    const int arow = tid >> 2;              // 0..63
    const int acol = (tid & 3) << 2;        // 0,4,8,12

    for (int k0 = 0; k0 < K; k0 += 16) {
        // A tile 64x16: one float4 per thread, guarded
        float4 av = make_float4(0.f, 0.f, 0.f, 0.f);
        if (m0 + arow < M)
            av = *(const float4*)(A + (size_t)(m0 + arow) * K + k0 + acol);
        {
            float h0 = wmma::__float_to_tf32(av.x);
            float h1 = wmma::__float_to_tf32(av.y);
            float h2 = wmma::__float_to_tf32(av.z);
            float h3 = wmma::__float_to_tf32(av.w);
            As_hi[arow][acol + 0] = h0; As_lo[arow][acol + 0] = wmma::__float_to_tf32(av.x - h0);
            As_hi[arow][acol + 1] = h1; As_lo[arow][acol + 1] = wmma::__float_to_tf32(av.y - h1);
            As_hi[arow][acol + 2] = h2; As_lo[arow][acol + 2] = wmma::__float_to_tf32(av.z - h2);
            As_hi[arow][acol + 3] = h3; As_lo[arow][acol + 3] = wmma::__float_to_tf32(av.w - h3);
        }
        // B tile 16x128: two float4 per thread
#pragma unroll
        for (int i = 0; i < 2; i++) {
            int idx  = tid + i * 256;       // 0..511
            int brow = idx >> 5;            // 0..15
            int bcol = (idx & 31) << 2;     // 0..124
            float4 bv = *(const float4*)(B + (size_t)(k0 + brow) * 128 + bcol);
            float h0 = wmma::__float_to_tf32(bv.x);
            float h1 = wmma::__float_to_tf32(bv.y);
            float h2 = wmma::__float_to_tf32(bv.z);
            float h3 = wmma::__float_to_tf32(bv.w);
            Bs_hi[brow][bcol + 0] = h0; Bs_lo[brow][bcol + 0] = wmma::__float_to_tf32(bv.x - h0);
            Bs_hi[brow][bcol + 1] = h1; Bs_lo[brow][bcol + 1] = wmma::__float_to_tf32(bv.y - h1);
            Bs_hi[brow][bcol + 2] = h2; Bs_lo[brow][bcol + 2] = wmma::__float_to_tf32(bv.z - h2);
            Bs_hi[brow][bcol + 3] = h3; Bs_lo[brow][bcol + 3] = wmma::__float_to_tf32(bv.w - h3);
        }
        __syncthreads();

#pragma unroll
        for (int ks = 0; ks < 16; ks += 8) {
            wmma::fragment<wmma::matrix_a, 16, 16, 8, wmma::precision::tf32, wmma::row_major> ah[2], al[2];
            wmma::fragment<wmma::matrix_b, 16, 16, 8, wmma::precision::tf32, wmma::row_major> bh[2], bl[2];
#pragma unroll
            for (int i = 0; i < 2; i++) {
                wmma::load_matrix_sync(ah[i], &As_hi[wm * 32 + i * 16][ks], 20);
                wmma::load_matrix_sync(al[i], &As_lo[wm * 32 + i * 16][ks], 20);
            }
#pragma unroll
            for (int j = 0; j < 2; j++) {
                wmma::load_matrix_sync(bh[j], &Bs_hi[ks][wn * 32 + j * 16], 136);
                wmma::load_matrix_sync(bl[j], &Bs_lo[ks][wn * 32 + j * 16], 136);
            }
#pragma unroll
            for (int i = 0; i < 2; i++)
#pragma unroll
                for (int j = 0; j < 2; j++) {
                    wmma::mma_sync(acc[i][j], ah[i], bh[j], acc[i][j]);
                    wmma::mma_sync(acc[i][j], ah[i], bl[j], acc[i][j]);
                    wmma::mma_sync(acc[i][j], al[i], bh[j], acc[i][j]);
                }
        }
        __syncthreads();
    }
    // unguarded store — C is padded to NPAD rows
#pragma unroll
    for (int i = 0; i < 2; i++)
#pragma unroll
        for (int j = 0; j < 2; j++) {
            int row = m0 + wm * 32 + i * 16;
            int col = wn * 32 + j * 16;
            wmma::store_matrix_sync(C + (size_t)row * 128 + col, acc[i][j], 128, wmma::mem_row_major);
        }
}

// ---------------------------------------------------------------------------
// Fused per-node aggregation: one warp per dst node.
// out[i,:] = relu( dinv[i]^2 * h[i,:] + sum_j nrm_j * h[src_j,:] + bias )
__global__ void k_agg(const float* __restrict__ h, const int* __restrict__ off,
                      const int* __restrict__ cnt, const int* __restrict__ csr_src,
                      const float* __restrict__ csr_nrm, const float* __restrict__ dinv,
                      const float* __restrict__ bias, float* __restrict__ outp, int n) {
    int node = blockIdx.x * (blockDim.x >> 5) + (threadIdx.x >> 5);
    int lane = threadIdx.x & 31;
    if (node >= n) return;

    float s = dinv[node];
    s = s * s;
    float4 acc = *(const float4*)(h + (size_t)node * HD + lane * 4);
    acc.x *= s; acc.y *= s; acc.z *= s; acc.w *= s;

    const int m    = cnt[node];
    const int base = off[node];
    int j = 0;
    for (; j + 4 <= m; j += 4) {
        int s0 = __ldg(csr_src + base + j + 0);
        int s1 = __ldg(csr_src + base + j + 1);
        int s2 = __ldg(csr_src + base + j + 2);
        int s3 = __ldg(csr_src + base + j + 3);
        float w0 = __ldg(csr_nrm + base + j + 0);
        float w1 = __ldg(csr_nrm + base + j + 1);
        float w2 = __ldg(csr_nrm + base + j + 2);
        float w3 = __ldg(csr_nrm + base + j + 3);
        float4 v0 = *(const float4*)(h + (size_t)s0 * HD + lane * 4);
        float4 v1 = *(const float4*)(h + (size_t)s1 * HD + lane * 4);
        float4 v2 = *(const float4*)(h + (size_t)s2 * HD + lane * 4);
        float4 v3 = *(const float4*)(h + (size_t)s3 * HD + lane * 4);
        acc.x = fmaf(w0, v0.x, acc.x); acc.y = fmaf(w0, v0.y, acc.y);
        acc.z = fmaf(w0, v0.z, acc.z); acc.w = fmaf(w0, v0.w, acc.w);
        acc.x = fmaf(w1, v1.x, acc.x); acc.y = fmaf(w1, v1.y, acc.y);
        acc.z = fmaf(w1, v1.z, acc.z); acc.w = fmaf(w1, v1.w, acc.w);
        acc.x = fmaf(w2, v2.x, acc.x); acc.y = fmaf(w2, v2.y, acc.y);
        acc.z = fmaf(w2, v2.z, acc.z); acc.w = fmaf(w2, v2.w, acc.w);
        acc.x = fmaf(w3, v3.x, acc.x); acc.y = fmaf(w3, v3.y, acc.y);
        acc.z = fmaf(w3, v3.z, acc.z); acc.w = fmaf(w3, v3.w, acc.w);
    }
    for (; j < m; j++) {
        int sj = __ldg(csr_src + base + j);
        float wj = __ldg(csr_nrm + base + j);
        float4 v = *(const float4*)(h + (size_t)sj * HD + lane * 4);
        acc.x = fmaf(wj, v.x, acc.x); acc.y = fmaf(wj, v.y, acc.y);
        acc.z = fmaf(wj, v.z, acc.z); acc.w = fmaf(wj, v.w, acc.w);
    }

    float4 bb = ((const float4*)bias)[lane];
    acc.x = fmaxf(acc.x + bb.x, 0.0f);
    acc.y = fmaxf(acc.y + bb.y, 0.0f);
    acc.z = fmaxf(acc.z + bb.z, 0.0f);
    acc.w = fmaxf(acc.w + bb.w, 0.0f);
    *(float4*)(outp + (size_t)node * HD + lane * 4) = acc;
}

// ---------------------------------------------------------------------------
// head: warp per node, logits = h @ fc_w + fc_b, softmax over 10 classes
__global__ void k_head(const float* __restrict__ h, const float* __restrict__ fcw,
                       const float* __restrict__ fcb, float* __restrict__ out, int n) {
    __shared__ float sw[HD * 10];
    __shared__ float sb[10];
    for (int i = threadIdx.x; i < HD * 10; i += blockDim.x) sw[i] = fcw[i];
    if (threadIdx.x < 10) sb[threadIdx.x] = fcb[threadIdx.x];
    __syncthreads();
    int node = (blockIdx.x * blockDim.x + threadIdx.x) >> 5;
    int lane = threadIdx.x & 31;
    if (node >= n) return;
    float4 hv = *(const float4*)(h + (size_t)node * HD + lane * 4);
    int k = lane * 4;
    float part[10];
#pragma unroll
    for (int c = 0; c < 10; c++) {
        part[c] = hv.x * sw[(k + 0) * 10 + c] + hv.y * sw[(k + 1) * 10 + c]
                + hv.z * sw[(k + 2) * 10 + c] + hv.w * sw[(k + 3) * 10 + c];
    }
#pragma unroll
    for (int off = 16; off; off >>= 1)
#pragma unroll
        for (int c = 0; c < 10; c++)
            part[c] += __shfl_xor_sync(0xffffffffu, part[c], off);
    if (lane == 0) {
        float m = -1e30f;
#pragma unroll
        for (int c = 0; c < 10; c++) { part[c] += sb[c]; m = fmaxf(m, part[c]); }
        float s = 0.0f;
#pragma unroll
        for (int c = 0; c < 10; c++) { part[c] = expf(part[c] - m); s += part[c]; }
        float inv = 1.0f / s;
#pragma unroll
        for (int c = 0; c < 10; c++) out[(size_t)node * 10 + c] = part[c] * inv;
    }
}

// ---------------------------------------------------------------------------
extern "C" void kernel_launch(void* const* d_in, const int* in_sizes, int n_in,
                              void* d_out, int out_size) {
    const float* x   = (const float*)d_in[0];
    const int*   ei  = (const int*)d_in[1];
    const float* ew  = (const float*)d_in[2];
    const float* W1  = (const float*)d_in[3];
    const float* b1  = (const float*)d_in[4];
    const float* W2  = (const float*)d_in[5];
    const float* b2  = (const float*)d_in[6];
    const float* W3  = (const float*)d_in[7];
    const float* b3  = (const float*)d_in[8];
    const float* fcw = (const float*)d_in[9];
    const float* fcb = (const float*)d_in[10];
    float* out = (float*)d_out;

    const int H = in_sizes[4];              // 128
    const int F = in_sizes[3] / H;          // 256
    const int N = in_sizes[0] / F;          // 50000
    const int E = in_sizes[2];              // 800000
    (void)n_in; (void)out_size;

    const int* src = ei;
    const int* dst = ei + E;

    float* deg;  cudaGetSymbolAddress((void**)&deg,  g_deg);
    float* dinv; cudaGetSymbolAddress((void**)&dinv, g_dinv);
    int*   cnt;  cudaGetSymbolAddress((void**)&cnt,  g_cnt);
    int*   off;  cudaGetSymbolAddress((void**)&off,  g_off);
    int*   head; cudaGetSymbolAddress((void**)&head, g_head);
    int*   bsum; cudaGetSymbolAddress((void**)&bsum, g_bsum);
    int*   csrs; cudaGetSymbolAddress((void**)&csrs, g_csr_src);
    float* csrn; cudaGetSymbolAddress((void**)&csrn, g_csr_nrm);
    float* hbuf; cudaGetSymbolAddress((void**)&hbuf, g_h);
    float* agg;  cudaGetSymbolAddress((void**)&agg,  g_agg);

    const int T = 256;
    const int scan_blocks = (N + 255) / 256;   // 196
    // norm + CSR precompute
    k_init     <<<(N + T - 1) / T, T>>>(deg, cnt, N);
    k_deg_count<<<(E + T - 1) / T, T>>>(dst, ew, deg, cnt, E);
    k_dinv     <<<(N + T - 1) / T, T>>>(deg, dinv, N);
    k_scan1    <<<scan_blocks, 256>>>(cnt, off, bsum, N);
    k_scan2    <<<1, 256>>>(bsum, scan_blocks);
    k_scan3    <<<scan_blocks, 256>>>(bsum, off, head, N);
    k_fill     <<<(E + T - 1) / T, T>>>(src, dst, ew, dinv, head, csrs, csrn, E);

    const int gemm_blocks = (N + 63) / 64;   // 782
    const int agg_blocks  = (N + 7) / 8;     // 8 warps per block

    // layer 1
    k_gemm_tc<<<gemm_blocks, 256>>>(x, W1, hbuf, N, F);
    k_agg    <<<agg_blocks, 256>>>(hbuf, off, cnt, csrs, csrn, dinv, b1, agg, N);
    // layer 2
    k_gemm_tc<<<gemm_blocks, 256>>>(agg, W2, hbuf, N, HD);
    k_agg    <<<agg_blocks, 256>>>(hbuf, off, cnt, csrs, csrn, dinv, b2, agg, N);
    // layer 3
    k_gemm_tc<<<gemm_blocks, 256>>>(agg, W3, hbuf, N, HD);
    k_agg    <<<agg_blocks, 256>>>(hbuf, off, cnt, csrs, csrn, dinv, b3, agg, N);
    // head
    k_head<<<(N * 32 + T - 1) / T, T>>>(agg, fcw, fcb, out, N);
}

// round 4
// speedup vs baseline: 1.4011x; 1.0824x over previous
#include <cuda_runtime.h>
#include <math.h>

#define NMAX 50000
#define NPAD 50048          // multiple of 64, padded scratch rows
#define EMAX 800000
#define HD   128

// Scratch (device globals — no allocation allowed)
__device__ __align__(16) float g_dinv[NMAX];
__device__ __align__(16) int   g_cnt[NMAX];
__device__ __align__(16) int   g_off[NMAX];
__device__ __align__(16) int   g_head[NMAX];
__device__ __align__(16) int   g_bsum[256];
__device__ __align__(16) int   g_csr_src[EMAX];
__device__ __align__(16) float g_csr_nrm[EMAX];   // ew, then dinv[src]*ew
__device__ __align__(16) float g_h[(size_t)NPAD * HD];    // GEMM output
__device__ __align__(16) float g_agg[(size_t)NPAD * HD];  // aggregation / layer output

// ---------------------------------------------------------------------------
__global__ void k_init(int* __restrict__ cnt, int n) {
    int i = blockIdx.x * blockDim.x + threadIdx.x;
    if (i < n) cnt[i] = 0;
}

__global__ void k_hist(const int* __restrict__ dst, int* __restrict__ cnt, int E) {
    int e = blockIdx.x * blockDim.x + threadIdx.x;
    if (e < E) atomicAdd(&cnt[dst[e]], 1);
}

// --- parallel exclusive scan of cnt -> off (3 small kernels) ---------------
__global__ void k_scan1(const int* __restrict__ cnt, int* __restrict__ off,
                        int* __restrict__ bsum, int n) {
    __shared__ int s[256];
    int i = blockIdx.x * 256 + threadIdx.x;
    int v = (i < n) ? cnt[i] : 0;
    s[threadIdx.x] = v;
    __syncthreads();
    for (int d = 1; d < 256; d <<= 1) {
        int t = (threadIdx.x >= d) ? s[threadIdx.x - d] : 0;
        __syncthreads();
        s[threadIdx.x] += t;
        __syncthreads();
    }
    if (i < n) off[i] = s[threadIdx.x] - v;     // exclusive within block
    if (threadIdx.x == 255) bsum[blockIdx.x] = s[255];
}

__global__ void k_scan2(int* __restrict__ bsum, int nb) {
    __shared__ int s[256];
    int t = threadIdx.x;
    int v = (t < nb) ? bsum[t] : 0;
    s[t] = v;
    __syncthreads();
    for (int d = 1; d < 256; d <<= 1) {
        int u = (t >= d) ? s[t - d] : 0;
        __syncthreads();
        s[t] += u;
        __syncthreads();
    }
    if (t < nb) bsum[t] = s[t] - v;             // exclusive block base
}

__global__ void k_scan3(const int* __restrict__ bsum, int* __restrict__ off,
                        int* __restrict__ head, int n) {
    int i = blockIdx.x * 256 + threadIdx.x;
    if (i < n) {
        int o = off[i] + bsum[blockIdx.x];
        off[i] = o;
        head[i] = o;
    }
}

// scatter edges into CSR order (no dinv dependency)
__global__ void k_fill(const int* __restrict__ src, const int* __restrict__ dst,
                       const float* __restrict__ ew, int* __restrict__ head,
                       int* __restrict__ csr_src, float* __restrict__ csr_w, int E) {
    int e = blockIdx.x * blockDim.x + threadIdx.x;
    if (e < E) {
        int d = dst[e];
        int p = atomicAdd(&head[d], 1);
        csr_src[p] = src[e];
        csr_w[p] = ew[e];
    }
}

// warp per node: deg = 1 + segment sum of csr_w; dinv = rsqrt(deg)
__global__ void k_deg_seg(const int* __restrict__ off, const int* __restrict__ cnt,
                          const float* __restrict__ csr_w, float* __restrict__ dinv, int n) {
    int node = blockIdx.x * (blockDim.x >> 5) + (threadIdx.x >> 5);
    int lane = threadIdx.x & 31;
    if (node >= n) return;
    int base = off[node], m = cnt[node];
    float s = 0.0f;
    for (int j = lane; j < m; j += 32) s += csr_w[base + j];
#pragma unroll
    for (int o = 16; o; o >>= 1) s += __shfl_xor_sync(0xffffffffu, s, o);
    if (lane == 0) {
        float d = 1.0f + s;
        dinv[node] = d > 0.0f ? rsqrtf(d) : 0.0f;
    }
}

// csr_w[e] *= dinv[csr_src[e]]  (in place)
__global__ void k_nrm(const int* __restrict__ csr_src, const float* __restrict__ dinv,
                      float* __restrict__ csr_w, int E) {
    int e = blockIdx.x * blockDim.x + threadIdx.x;
    if (e < E) csr_w[e] *= dinv[csr_src[e]];
}

// ---------------------------------------------------------------------------
// SIMT fp32 GEMM, double-buffered: C[M,128] = A[M,K] @ B[K,128], row-major.
// BM=64, BN=128, BK=16, 256 threads, 4x8 register tile, 1 sync per k-tile.
__global__ __launch_bounds__(256) void k_gemm(const float* __restrict__ A,
                                              const float* __restrict__ B,
                                              float* __restrict__ C, int M, int K) {
    __shared__ float As[2][16][68];    // [buf][k][m], padded
    __shared__ float Bs[2][16][136];   // [buf][k][n], padded
    const int tid = threadIdx.x;
    const int ty = tid >> 4;        // 0..15 row group
    const int tx = tid & 15;        // 0..15 col group
    const int m0 = blockIdx.x * 64;

    const int arow = tid >> 2;          // 0..63
    const int akc  = (tid & 3) << 2;    // 0,4,8,12
    const int brow0 = tid >> 5;         // 0..7
    const int bcol  = (tid & 31) << 2;  // 0..124

    float acc[4][8];
#pragma unroll
    for (int i = 0; i < 4; i++)
#pragma unroll
        for (int j = 0; j < 8; j++) acc[i][j] = 0.0f;

    const int nt = K >> 4;

    // prologue: tile 0 -> buffer 0
    {
        float4 av = make_float4(0.f, 0.f, 0.f, 0.f);
        if (m0 + arow < M)
            av = *(const float4*)(A + (size_t)(m0 + arow) * K + akc);
        As[0][akc + 0][arow] = av.x;
        As[0][akc + 1][arow] = av.y;
        As[0][akc + 2][arow] = av.z;
        As[0][akc + 3][arow] = av.w;
        float4 b0 = *(const float4*)(B + (size_t)brow0 * 128 + bcol);
        float4 b1 = *(const float4*)(B + (size_t)(brow0 + 8) * 128 + bcol);
        *(float4*)&Bs[0][brow0][bcol]     = b0;
        *(float4*)&Bs[0][brow0 + 8][bcol] = b1;
    }
    __syncthreads();

    for (int t = 0; t < nt; t++) {
        const int cur = t & 1, nxt = cur ^ 1;
        float4 av, b0, b1;
        const bool more = (t + 1 < nt);
        if (more) {
            const int k0 = (t + 1) << 4;
            av = make_float4(0.f, 0.f, 0.f, 0.f);
            if (m0 + arow < M)
                av = *(const float4*)(A + (size_t)(m0 + arow) * K + k0 + akc);
            b0 = *(const float4*)(B + (size_t)(k0 + brow0) * 128 + bcol);
            b1 = *(const float4*)(B + (size_t)(k0 + brow0 + 8) * 128 + bcol);
        }
#pragma unroll
        for (int k = 0; k < 16; k++) {
            float a[4], b[8];
#pragma unroll
            for (int i = 0; i < 4; i++) a[i] = As[cur][k][ty * 4 + i];
#pragma unroll
            for (int j = 0; j < 8; j++) b[j] = Bs[cur][k][tx * 8 + j];
#pragma unroll
            for (int i = 0; i < 4; i++)
#pragma unroll
                for (int j = 0; j < 8; j++)
                    acc[i][j] = fmaf(a[i], b[j], acc[i][j]);
        }
        if (more) {
            As[nxt][akc + 0][arow] = av.x;
            As[nxt][akc + 1][arow] = av.y;
            As[nxt][akc + 2][arow] = av.z;
            As[nxt][akc + 3][arow] = av.w;
            *(float4*)&Bs[nxt][brow0][bcol]     = b0;
            *(float4*)&Bs[nxt][brow0 + 8][bcol] = b1;
        }
        __syncthreads();
    }
    // C padded to NPAD rows -> unguarded store
#pragma unroll
    for (int i = 0; i < 4; i++) {
        int grow = m0 + ty * 4 + i;
        float* cp = C + (size_t)grow * 128 + tx * 8;
        *(float4*)cp       = make_float4(acc[i][0], acc[i][1], acc[i][2], acc[i][3]);
        *(float4*)(cp + 4) = make_float4(acc[i][4], acc[i][5], acc[i][6], acc[i][7]);
    }
}

// ---------------------------------------------------------------------------
// Fused per-node aggregation: one warp per dst node.
// out[i,:] = relu( dinv[i]*( dinv[i]*h[i,:] + sum_j w_j*h[src_j,:] ) + bias )
// where w_j = dinv[src_j] * ew_j  (precomputed in csr_nrm)
__global__ void k_agg(const float* __restrict__ h, const int* __restrict__ off,
                      const int* __restrict__ cnt, const int* __restrict__ csr_src,
                      const float* __restrict__ csr_nrm, const float* __restrict__ dinv,
                      const float* __restrict__ bias, float* __restrict__ outp, int n) {
    int node = blockIdx.x * (blockDim.x >> 5) + (threadIdx.x >> 5);
    int lane = threadIdx.x & 31;
    if (node >= n) return;

    const float di = dinv[node];
    float4 acc = *(const float4*)(h + (size_t)node * HD + lane * 4);
    acc.x *= di; acc.y *= di; acc.z *= di; acc.w *= di;

    const int m    = cnt[node];
    const int base = off[node];
    int j = 0;
    for (; j + 4 <= m; j += 4) {
        int s0 = __ldg(csr_src + base + j + 0);
        int s1 = __ldg(csr_src + base + j + 1);
        int s2 = __ldg(csr_src + base + j + 2);
        int s3 = __ldg(csr_src + base + j + 3);
        float w0 = __ldg(csr_nrm + base + j + 0);
        float w1 = __ldg(csr_nrm + base + j + 1);
        float w2 = __ldg(csr_nrm + base + j + 2);
        float w3 = __ldg(csr_nrm + base + j + 3);
        float4 v0 = *(const float4*)(h + (size_t)s0 * HD + lane * 4);
        float4 v1 = *(const float4*)(h + (size_t)s1 * HD + lane * 4);
        float4 v2 = *(const float4*)(h + (size_t)s2 * HD + lane * 4);
        float4 v3 = *(const float4*)(h + (size_t)s3 * HD + lane * 4);
        acc.x = fmaf(w0, v0.x, acc.x); acc.y = fmaf(w0, v0.y, acc.y);
        acc.z = fmaf(w0, v0.z, acc.z); acc.w = fmaf(w0, v0.w, acc.w);
        acc.x = fmaf(w1, v1.x, acc.x); acc.y = fmaf(w1, v1.y, acc.y);
        acc.z = fmaf(w1, v1.z, acc.z); acc.w = fmaf(w1, v1.w, acc.w);
        acc.x = fmaf(w2, v2.x, acc.x); acc.y = fmaf(w2, v2.y, acc.y);
        acc.z = fmaf(w2, v2.z, acc.z); acc.w = fmaf(w2, v2.w, acc.w);
        acc.x = fmaf(w3, v3.x, acc.x); acc.y = fmaf(w3, v3.y, acc.y);
        acc.z = fmaf(w3, v3.z, acc.z); acc.w = fmaf(w3, v3.w, acc.w);
    }
    for (; j < m; j++) {
        int sj = __ldg(csr_src + base + j);
        float wj = __ldg(csr_nrm + base + j);
        float4 v = *(const float4*)(h + (size_t)sj * HD + lane * 4);
        acc.x = fmaf(wj, v.x, acc.x); acc.y = fmaf(wj, v.y, acc.y);
        acc.z = fmaf(wj, v.z, acc.z); acc.w = fmaf(wj, v.w, acc.w);
    }

    float4 bb = ((const float4*)bias)[lane];
    acc.x = fmaxf(fmaf(di, acc.x, bb.x), 0.0f);
    acc.y = fmaxf(fmaf(di, acc.y, bb.y), 0.0f);
    acc.z = fmaxf(fmaf(di, acc.z, bb.z), 0.0f);
    acc.w = fmaxf(fmaf(di, acc.w, bb.w), 0.0f);
    *(float4*)(outp + (size_t)node * HD + lane * 4) = acc;
}

// ---------------------------------------------------------------------------
// head: warp per node, logits = h @ fc_w + fc_b, softmax over 10 classes
__global__ void k_head(const float* __restrict__ h, const float* __restrict__ fcw,
                       const float* __restrict__ fcb, float* __restrict__ out, int n) {
    __shared__ float sw[HD * 10];
    __shared__ float sb[10];
    for (int i = threadIdx.x; i < HD * 10; i += blockDim.x) sw[i] = fcw[i];
    if (threadIdx.x < 10) sb[threadIdx.x] = fcb[threadIdx.x];
    __syncthreads();
    int node = (blockIdx.x * blockDim.x + threadIdx.x) >> 5;
    int lane = threadIdx.x & 31;
    if (node >= n) return;
    float4 hv = *(const float4*)(h + (size_t)node * HD + lane * 4);
    int k = lane * 4;
    float part[10];
#pragma unroll
    for (int c = 0; c < 10; c++) {
        part[c] = hv.x * sw[(k + 0) * 10 + c] + hv.y * sw[(k + 1) * 10 + c]
                + hv.z * sw[(k + 2) * 10 + c] + hv.w * sw[(k + 3) * 10 + c];
    }
#pragma unroll
    for (int off = 16; off; off >>= 1)
#pragma unroll
        for (int c = 0; c < 10; c++)
            part[c] += __shfl_xor_sync(0xffffffffu, part[c], off);
    if (lane == 0) {
        float m = -1e30f;
#pragma unroll
        for (int c = 0; c < 10; c++) { part[c] += sb[c]; m = fmaxf(m, part[c]); }
        float s = 0.0f;
#pragma unroll
        for (int c = 0; c < 10; c++) { part[c] = expf(part[c] - m); s += part[c]; }
        float inv = 1.0f / s;
#pragma unroll
        for (int c = 0; c < 10; c++) out[(size_t)node * 10 + c] = part[c] * inv;
    }
}

// ---------------------------------------------------------------------------
extern "C" void kernel_launch(void* const* d_in, const int* in_sizes, int n_in,
                              void* d_out, int out_size) {
    const float* x   = (const float*)d_in[0];
    const int*   ei  = (const int*)d_in[1];
    const float* ew  = (const float*)d_in[2];
    const float* W1  = (const float*)d_in[3];
    const float* b1  = (const float*)d_in[4];
    const float* W2  = (const float*)d_in[5];
    const float* b2  = (const float*)d_in[6];
    const float* W3  = (const float*)d_in[7];
    const float* b3  = (const float*)d_in[8];
    const float* fcw = (const float*)d_in[9];
    const float* fcb = (const float*)d_in[10];
    float* out = (float*)d_out;

    const int H = in_sizes[4];              // 128
    const int F = in_sizes[3] / H;          // 256
    const int N = in_sizes[0] / F;          // 50000
    const int E = in_sizes[2];              // 800000
    (void)n_in; (void)out_size;

    const int* src = ei;
    const int* dst = ei + E;

    float* dinv; cudaGetSymbolAddress((void**)&dinv, g_dinv);
    int*   cnt;  cudaGetSymbolAddress((void**)&cnt,  g_cnt);
    int*   off;  cudaGetSymbolAddress((void**)&off,  g_off);
    int*   head; cudaGetSymbolAddress((void**)&head, g_head);
    int*   bsum; cudaGetSymbolAddress((void**)&bsum, g_bsum);
    int*   csrs; cudaGetSymbolAddress((void**)&csrs, g_csr_src);
    float* csrn; cudaGetSymbolAddress((void**)&csrn, g_csr_nrm);
    float* hbuf; cudaGetSymbolAddress((void**)&hbuf, g_h);
    float* agg;  cudaGetSymbolAddress((void**)&agg,  g_agg);

    const int T = 256;
    const int scan_blocks = (N + 255) / 256;   // 196
    const int agg_blocks  = (N + 7) / 8;       // 8 warps per block
    // CSR precompute (no float atomics)
    k_init   <<<(N + T - 1) / T, T>>>(cnt, N);
    k_hist   <<<(E + T - 1) / T, T>>>(dst, cnt, E);
    k_scan1  <<<scan_blocks, 256>>>(cnt, off, bsum, N);
    k_scan2  <<<1, 256>>>(bsum, scan_blocks);
    k_scan3  <<<scan_blocks, 256>>>(bsum, off, head, N);
    k_fill   <<<(E + T - 1) / T, T>>>(src, dst, ew, head, csrs, csrn, E);
    k_deg_seg<<<agg_blocks, 256>>>(off, cnt, csrn, dinv, N);
    k_nrm    <<<(E + T - 1) / T, T>>>(csrs, dinv, csrn, E);

    const int gemm_blocks = (N + 63) / 64;   // 782

    // layer 1
    k_gemm<<<gemm_blocks, 256>>>(x, W1, hbuf, N, F);
    k_agg <<<agg_blocks, 256>>>(hbuf, off, cnt, csrs, csrn, dinv, b1, agg, N);
    // layer 2
    k_gemm<<<gemm_blocks, 256>>>(agg, W2, hbuf, N, HD);
    k_agg <<<agg_blocks, 256>>>(hbuf, off, cnt, csrs, csrn, dinv, b2, agg, N);
    // layer 3
    k_gemm<<<gemm_blocks, 256>>>(agg, W3, hbuf, N, HD);
    k_agg <<<agg_blocks, 256>>>(hbuf, off, cnt, csrs, csrn, dinv, b3, agg, N);
    // head
    k_head<<<(N * 32 + T - 1) / T, T>>>(agg, fcw, fcb, out, N);
}

// round 6
// speedup vs baseline: 1.6493x; 1.1772x over previous
#include <cuda_runtime.h>
#include <cuda_bf16.h>
#include <math.h>

#define NMAX 50000
#define NPAD 50048          // multiple of 128 for unguarded MMA tiles
#define EMAX 800000
#define HD   128

// Scratch (device globals — no allocation allowed)
__device__ __align__(16) float g_deg[NMAX];
__device__ __align__(16) float g_dinv[NMAX];
__device__ __align__(16) int   g_cnt[NMAX];
__device__ __align__(16) int   g_off[NMAX];
__device__ __align__(16) int   g_head[NMAX];
__device__ __align__(16) int   g_bsum[256];
__device__ __align__(16) int   g_csr_src[EMAX];
__device__ __align__(16) float g_csr_nrm[EMAX];
__device__ __align__(16) float g_h[(size_t)NPAD * HD];    // GEMM output
__device__ __align__(16) float g_agg[(size_t)NPAD * HD];  // aggregation / layer output
// Pre-swizzled bf16 weight panels, [n=128][k] K-major, BK=32 chunks of 128x80B.
// L1 (K=256): [0, 81920); L2: [81920, 122880); L3: [122880, 163840)
__device__ __align__(16) unsigned char g_wp_hi[163840];
__device__ __align__(16) unsigned char g_wp_lo[163840];

// ---------------------------------------------------------------------------
__device__ __forceinline__ unsigned smem_u32(const void* p) {
    unsigned a;
    asm("{ .reg .u64 t; cvta.to.shared.u64 t, %1; cvt.u32.u64 %0, t; }" : "=r"(a) : "l"(p));
    return a;
}
__device__ __forceinline__ void ldsm4(unsigned* r, unsigned addr) {
    asm volatile("ldmatrix.sync.aligned.m8n8.x4.shared.b16 {%0,%1,%2,%3}, [%4];"
                 : "=r"(r[0]), "=r"(r[1]), "=r"(r[2]), "=r"(r[3]) : "r"(addr));
}
__device__ __forceinline__ void mma16816(float* c, const unsigned* a, unsigned b0, unsigned b1) {
    asm volatile("mma.sync.aligned.m16n8k16.row.col.f32.bf16.bf16.f32 "
                 "{%0,%1,%2,%3}, {%4,%5,%6,%7}, {%8,%9}, {%0,%1,%2,%3};"
                 : "+f"(c[0]), "+f"(c[1]), "+f"(c[2]), "+f"(c[3])
                 : "r"(a[0]), "r"(a[1]), "r"(a[2]), "r"(a[3]), "r"(b0), "r"(b1));
}
__device__ __forceinline__ void cpasync16(unsigned saddr, const void* gaddr) {
    asm volatile("cp.async.cg.shared.global [%0], [%1], 16;" :: "r"(saddr), "l"(gaddr));
}
#define CP_COMMIT() asm volatile("cp.async.commit_group;" ::: "memory")
#define CP_WAIT()   asm volatile("cp.async.wait_group 0;" ::: "memory")

// panel/tile byte offset inside a BK=32 chunk: row-major [row][k], stride 80B
__device__ __forceinline__ unsigned chunk_off(int row, int k) {
    return (unsigned)(row * 80 + k * 2);
}

// ---------------------------------------------------------------------------
__global__ void k_init(float* __restrict__ deg, int* __restrict__ cnt, int n) {
    int i = blockIdx.x * blockDim.x + threadIdx.x;
    if (i < n) { deg[i] = 1.0f; cnt[i] = 0; }   // self-loop weight 1
}

__global__ void k_hist(const int* __restrict__ dst, const float* __restrict__ ew,
                       float* __restrict__ deg, int* __restrict__ cnt, int E) {
    int e = blockIdx.x * blockDim.x + threadIdx.x;
    if (e < E) {
        int d = dst[e];
        atomicAdd(&deg[d], ew[e]);
        atomicAdd(&cnt[d], 1);
    }
}

__global__ void k_dinv(const float* __restrict__ deg, float* __restrict__ dinv, int n) {
    int i = blockIdx.x * blockDim.x + threadIdx.x;
    if (i < n) {
        float d = deg[i];
        dinv[i] = d > 0.0f ? rsqrtf(d) : 0.0f;
    }
}

__global__ void k_scan1(const int* __restrict__ cnt, int* __restrict__ off,
                        int* __restrict__ bsum, int n) {
    __shared__ int s[256];
    int i = blockIdx.x * 256 + threadIdx.x;
    int v = (i < n) ? cnt[i] : 0;
    s[threadIdx.x] = v;
    __syncthreads();
    for (int d = 1; d < 256; d <<= 1) {
        int t = (threadIdx.x >= d) ? s[threadIdx.x - d] : 0;
        __syncthreads();
        s[threadIdx.x] += t;
        __syncthreads();
    }
    if (i < n) off[i] = s[threadIdx.x] - v;
    if (threadIdx.x == 255) bsum[blockIdx.x] = s[255];
}

__global__ void k_scan2(int* __restrict__ bsum, int nb) {
    __shared__ int s[256];
    int t = threadIdx.x;
    int v = (t < nb) ? bsum[t] : 0;
    s[t] = v;
    __syncthreads();
    for (int d = 1; d < 256; d <<= 1) {
        int u = (t >= d) ? s[t - d] : 0;
        __syncthreads();
        s[t] += u;
        __syncthreads();
    }
    if (t < nb) bsum[t] = s[t] - v;
}

__global__ void k_scan3(const int* __restrict__ bsum, int* __restrict__ off,
                        int* __restrict__ head, int n) {
    int i = blockIdx.x * 256 + threadIdx.x;
    if (i < n) {
        int o = off[i] + bsum[blockIdx.x];
        off[i] = o;
        head[i] = o;
    }
}

// scatter edges into CSR order with normalized weight dinv[src]*ew
__global__ void k_fill(const int* __restrict__ src, const int* __restrict__ dst,
                       const float* __restrict__ ew, const float* __restrict__ dinv,
                       int* __restrict__ head, int* __restrict__ csr_src,
                       float* __restrict__ csr_w, int E) {
    int e = blockIdx.x * blockDim.x + threadIdx.x;
    if (e < E) {
        int s = src[e], d = dst[e];
        int p = atomicAdd(&head[d], 1);
        csr_src[p] = s;
        csr_w[p] = dinv[s] * ew[e];
    }
}

// ---------------------------------------------------------------------------
// Convert W[K][128] fp32 -> split-bf16 panels [n][k] K-major, BK=32 chunked, 80B row stride
__global__ void k_wconv(const float* __restrict__ W, unsigned char* __restrict__ hi,
                        unsigned char* __restrict__ lo, int K) {
    int e = blockIdx.x * 256 + threadIdx.x;
    if (e >= K * 128) return;
    int k = e >> 7, n = e & 127;
    float x = W[e];
    __nv_bfloat16 h = __float2bfloat16(x);
    __nv_bfloat16 l = __float2bfloat16(x - __bfloat162float(h));
    unsigned so = (unsigned)(k >> 5) * 10240u + chunk_off(n, k & 31);
    *(__nv_bfloat16*)(hi + so) = h;
    *(__nv_bfloat16*)(lo + so) = l;
}

// ---------------------------------------------------------------------------
// mma.sync bf16-split GEMM: C[NPAD,128] = A[*,K] @ W[K,128].
// CTA tile 128x128, BK=32 double-buffered, 256 threads (8 warps, 2x4), warp tile 64x32.
// Stage layout (per buffer, 40960 B): A_hi[128x80B] | A_lo | B_hi | B_lo
__global__ __launch_bounds__(256) void k_gemm_mma(
    const float* __restrict__ A, const unsigned char* __restrict__ wp_hi,
    const unsigned char* __restrict__ wp_lo, float* __restrict__ C, int Mreal, int K) {
    extern __shared__ __align__(16) unsigned char smem[];
    const unsigned sbase = smem_u32(smem);

    const int tid  = threadIdx.x;
    const int wid  = tid >> 5;
    const int lane = tid & 31;
    const int wm   = wid >> 2;      // 0..1
    const int wn   = wid & 3;       // 0..3
    const int m0   = blockIdx.x * 128;

    // A staging geometry: 1024 float4 per tile (row = f4>>3, klocal = (f4&7)*4)
    const int arow = tid >> 1;                 // rows: thread handles rows tid>>1 +  ... recompute per it
    (void)arow;

    float acc[4][4][4];
#pragma unroll
    for (int i = 0; i < 4; i++)
#pragma unroll
        for (int j = 0; j < 4; j++)
#pragma unroll
            for (int r = 0; r < 4; r++) acc[i][j][r] = 0.0f;

    const int nst = K >> 5;

    // ---- helpers as lambdas ----
    auto issueB = [&](int buf, int kc) {
        const unsigned bh = sbase + buf * 40960 + 20480;
        const unsigned bl = bh + 10240;
        const unsigned char* gh = wp_hi + (size_t)kc * 10240;
        const unsigned char* gl = wp_lo + (size_t)kc * 10240;
        for (int i = tid; i < 640; i += 256) {
            cpasync16(bh + i * 16, gh + i * 16);
            cpasync16(bl + i * 16, gl + i * 16);
        }
        CP_COMMIT();
    };
    auto loadAregs = [&](int kc, float4* v) {
#pragma unroll
        for (int it = 0; it < 4; it++) {
            int f4 = it * 256 + tid;
            int row = f4 >> 3, kl = (f4 & 7) << 2;
            int gr = m0 + row;
            v[it] = make_float4(0.f, 0.f, 0.f, 0.f);
            if (gr < Mreal)
                v[it] = *(const float4*)(A + (size_t)gr * K + (kc << 5) + kl);
        }
    };
    auto storeA = [&](int buf, const float4* v) {
        unsigned ah = sbase + buf * 40960;
        unsigned al = ah + 10240;
        unsigned char* bp = smem + buf * 40960;
#pragma unroll
        for (int it = 0; it < 4; it++) {
            int f4 = it * 256 + tid;
            int row = f4 >> 3, kl = (f4 & 7) << 2;
            float4 x = v[it];
            __nv_bfloat16 hx = __float2bfloat16(x.x), hy = __float2bfloat16(x.y);
            __nv_bfloat16 hz = __float2bfloat16(x.z), hw = __float2bfloat16(x.w);
            __nv_bfloat16 lx = __float2bfloat16(x.x - __bfloat162float(hx));
            __nv_bfloat16 ly = __float2bfloat16(x.y - __bfloat162float(hy));
            __nv_bfloat16 lz = __float2bfloat16(x.z - __bfloat162float(hz));
            __nv_bfloat16 lw = __float2bfloat16(x.w - __bfloat162float(hw));
            unsigned h0 = (unsigned)__bfloat16_as_ushort(hx) | ((unsigned)__bfloat16_as_ushort(hy) << 16);
            unsigned h1 = (unsigned)__bfloat16_as_ushort(hz) | ((unsigned)__bfloat16_as_ushort(hw) << 16);
            unsigned l0 = (unsigned)__bfloat16_as_ushort(lx) | ((unsigned)__bfloat16_as_ushort(ly) << 16);
            unsigned l1 = (unsigned)__bfloat16_as_ushort(lz) | ((unsigned)__bfloat16_as_ushort(lw) << 16);
            unsigned off = chunk_off(row, kl);
            *(uint2*)(bp + off)         = make_uint2(h0, h1);
            *(uint2*)(bp + 10240 + off) = make_uint2(l0, l1);
        }
        (void)ah; (void)al;
    };
    auto compute = [&](int buf) {
        const unsigned aH = sbase + buf * 40960;
        const unsigned aL = aH + 10240;
        const unsigned bH = aH + 20480;
        const unsigned bL = aH + 30720;
        const int rsel = lane & 15;
        const unsigned koff16 = ((lane >> 4) << 4);   // 0 or 16 bytes (k +8 elements)
#pragma unroll
        for (int s = 0; s < 2; s++) {
            const unsigned kb = (unsigned)(s * 32) + koff16;
            unsigned ah[4][4], al[4][4], bh[2][4], bl[2][4];
#pragma unroll
            for (int mi = 0; mi < 4; mi++) {
                unsigned ro = chunk_off(wm * 64 + mi * 16 + rsel, 0) + kb;
                ldsm4(ah[mi], aH + ro);
                ldsm4(al[mi], aL + ro);
            }
#pragma unroll
            for (int g = 0; g < 2; g++) {
                unsigned ro = chunk_off(wn * 32 + g * 16 + rsel, 0) + kb;
                ldsm4(bh[g], bH + ro);
                ldsm4(bl[g], bL + ro);
            }
#pragma unroll
            for (int mi = 0; mi < 4; mi++)
#pragma unroll
                for (int nj = 0; nj < 4; nj++) {
                    int g = nj >> 1, o = nj & 1;
                    mma16816(acc[mi][nj], ah[mi], bh[g][o], bh[g][o + 2]);
                    mma16816(acc[mi][nj], ah[mi], bl[g][o], bl[g][o + 2]);
                    mma16816(acc[mi][nj], al[mi], bh[g][o], bh[g][o + 2]);
                }
        }
    };

    // ---- pipeline ----
    float4 stage[4];
    issueB(0, 0);
    loadAregs(0, stage);
    storeA(0, stage);
    CP_WAIT();
    __syncthreads();

    for (int kc = 0; kc < nst; kc++) {
        const int cur = kc & 1, nxt = cur ^ 1;
        const bool more = (kc + 1 < nst);
        if (more) {
            issueB(nxt, kc + 1);
            loadAregs(kc + 1, stage);
        }
        compute(cur);
        if (more) {
            storeA(nxt, stage);
            CP_WAIT();
        }
        __syncthreads();
    }

    // ---- epilogue: unguarded (C padded to NPAD rows) ----
#pragma unroll
    for (int mi = 0; mi < 4; mi++) {
        int gm = m0 + wm * 64 + mi * 16 + (lane >> 2);
#pragma unroll
        for (int nj = 0; nj < 4; nj++) {
            int col = wn * 32 + nj * 8 + (lane & 3) * 2;
            *(float2*)(C + (size_t)gm * 128 + col)       = make_float2(acc[mi][nj][0], acc[mi][nj][1]);
            *(float2*)(C + (size_t)(gm + 8) * 128 + col) = make_float2(acc[mi][nj][2], acc[mi][nj][3]);
        }
    }
}

// ---------------------------------------------------------------------------
// Fused per-node aggregation: one warp per dst node.
// out[i,:] = relu( dinv[i]*( dinv[i]*h[i,:] + sum_j w_j*h[src_j,:] ) + bias )
__global__ void k_agg(const float* __restrict__ h, const int* __restrict__ off,
                      const int* __restrict__ cnt, const int* __restrict__ csr_src,
                      const float* __restrict__ csr_nrm, const float* __restrict__ dinv,
                      const float* __restrict__ bias, float* __restrict__ outp, int n) {
    int node = blockIdx.x * (blockDim.x >> 5) + (threadIdx.x >> 5);
    int lane = threadIdx.x & 31;
    if (node >= n) return;

    const float di = dinv[node];
    float4 acc = *(const float4*)(h + (size_t)node * HD + lane * 4);
    acc.x *= di; acc.y *= di; acc.z *= di; acc.w *= di;

    const int m    = cnt[node];
    const int base = off[node];
    int j = 0;
    for (; j + 4 <= m; j += 4) {
        int s0 = __ldg(csr_src + base + j + 0);
        int s1 = __ldg(csr_src + base + j + 1);
        int s2 = __ldg(csr_src + base + j + 2);
        int s3 = __ldg(csr_src + base + j + 3);
        float w0 = __ldg(csr_nrm + base + j + 0);
        float w1 = __ldg(csr_nrm + base + j + 1);
        float w2 = __ldg(csr_nrm + base + j + 2);
        float w3 = __ldg(csr_nrm + base + j + 3);
        float4 v0 = *(const float4*)(h + (size_t)s0 * HD + lane * 4);
        float4 v1 = *(const float4*)(h + (size_t)s1 * HD + lane * 4);
        float4 v2 = *(const float4*)(h + (size_t)s2 * HD + lane * 4);
        float4 v3 = *(const float4*)(h + (size_t)s3 * HD + lane * 4);
        acc.x = fmaf(w0, v0.x, acc.x); acc.y = fmaf(w0, v0.y, acc.y);
        acc.z = fmaf(w0, v0.z, acc.z); acc.w = fmaf(w0, v0.w, acc.w);
        acc.x = fmaf(w1, v1.x, acc.x); acc.y = fmaf(w1, v1.y, acc.y);
        acc.z = fmaf(w1, v1.z, acc.z); acc.w = fmaf(w1, v1.w, acc.w);
        acc.x = fmaf(w2, v2.x, acc.x); acc.y = fmaf(w2, v2.y, acc.y);
        acc.z = fmaf(w2, v2.z, acc.z); acc.w = fmaf(w2, v2.w, acc.w);
        acc.x = fmaf(w3, v3.x, acc.x); acc.y = fmaf(w3, v3.y, acc.y);
        acc.z = fmaf(w3, v3.z, acc.z); acc.w = fmaf(w3, v3.w, acc.w);
    }
    for (; j < m; j++) {
        int sj = __ldg(csr_src + base + j);
        float wj = __ldg(csr_nrm + base + j);
        float4 v = *(const float4*)(h + (size_t)sj * HD + lane * 4);
        acc.x = fmaf(wj, v.x, acc.x); acc.y = fmaf(wj, v.y, acc.y);
        acc.z = fmaf(wj, v.z, acc.z); acc.w = fmaf(wj, v.w, acc.w);
    }

    float4 bb = ((const float4*)bias)[lane];
    acc.x = fmaxf(fmaf(di, acc.x, bb.x), 0.0f);
    acc.y = fmaxf(fmaf(di, acc.y, bb.y), 0.0f);
    acc.z = fmaxf(fmaf(di, acc.z, bb.z), 0.0f);
    acc.w = fmaxf(fmaf(di, acc.w, bb.w), 0.0f);
    *(float4*)(outp + (size_t)node * HD + lane * 4) = acc;
}

// ---------------------------------------------------------------------------
__global__ void k_head(const float* __restrict__ h, const float* __restrict__ fcw,
                       const float* __restrict__ fcb, float* __restrict__ out, int n) {
    __shared__ float sw[HD * 10];
    __shared__ float sb[10];
    for (int i = threadIdx.x; i < HD * 10; i += blockDim.x) sw[i] = fcw[i];
    if (threadIdx.x < 10) sb[threadIdx.x] = fcb[threadIdx.x];
    __syncthreads();
    int node = (blockIdx.x * blockDim.x + threadIdx.x) >> 5;
    int lane = threadIdx.x & 31;
    if (node >= n) return;
    float4 hv = *(const float4*)(h + (size_t)node * HD + lane * 4);
    int k = lane * 4;
    float part[10];
#pragma unroll
    for (int c = 0; c < 10; c++) {
        part[c] = hv.x * sw[(k + 0) * 10 + c] + hv.y * sw[(k + 1) * 10 + c]
                + hv.z * sw[(k + 2) * 10 + c] + hv.w * sw[(k + 3) * 10 + c];
    }
#pragma unroll
    for (int off = 16; off; off >>= 1)
#pragma unroll
        for (int c = 0; c < 10; c++)
            part[c] += __shfl_xor_sync(0xffffffffu, part[c], off);
    if (lane == 0) {
        float m = -1e30f;
#pragma unroll
        for (int c = 0; c < 10; c++) { part[c] += sb[c]; m = fmaxf(m, part[c]); }
        float s = 0.0f;
#pragma unroll
        for (int c = 0; c < 10; c++) { part[c] = expf(part[c] - m); s += part[c]; }
        float inv = 1.0f / s;
#pragma unroll
        for (int c = 0; c < 10; c++) out[(size_t)node * 10 + c] = part[c] * inv;
    }
}

// ---------------------------------------------------------------------------
extern "C" void kernel_launch(void* const* d_in, const int* in_sizes, int n_in,
                              void* d_out, int out_size) {
    const float* x   = (const float*)d_in[0];
    const int*   ei  = (const int*)d_in[1];
    const float* ew  = (const float*)d_in[2];
    const float* W1  = (const float*)d_in[3];
    const float* b1  = (const float*)d_in[4];
    const float* W2  = (const float*)d_in[5];
    const float* b2  = (const float*)d_in[6];
    const float* W3  = (const float*)d_in[7];
    const float* b3  = (const float*)d_in[8];
    const float* fcw = (const float*)d_in[9];
    const float* fcb = (const float*)d_in[10];
    float* out = (float*)d_out;

    const int H = in_sizes[4];              // 128
    const int F = in_sizes[3] / H;          // 256
    const int N = in_sizes[0] / F;          // 50000
    const int E = in_sizes[2];              // 800000
    (void)n_in; (void)out_size;

    const int* src = ei;
    const int* dst = ei + E;

    float* deg;  cudaGetSymbolAddress((void**)&deg,  g_deg);
    float* dinv; cudaGetSymbolAddress((void**)&dinv, g_dinv);
    int*   cnt;  cudaGetSymbolAddress((void**)&cnt,  g_cnt);
    int*   off;  cudaGetSymbolAddress((void**)&off,  g_off);
    int*   head; cudaGetSymbolAddress((void**)&head, g_head);
    int*   bsum; cudaGetSymbolAddress((void**)&bsum, g_bsum);
    int*   csrs; cudaGetSymbolAddress((void**)&csrs, g_csr_src);
    float* csrn; cudaGetSymbolAddress((void**)&csrn, g_csr_nrm);
    float* hbuf; cudaGetSymbolAddress((void**)&hbuf, g_h);
    float* agg;  cudaGetSymbolAddress((void**)&agg,  g_agg);
    unsigned char* wph; cudaGetSymbolAddress((void**)&wph, g_wp_hi);
    unsigned char* wpl; cudaGetSymbolAddress((void**)&wpl, g_wp_lo);

    const int SMEM_GEMM = 81920;
    static int attr_done = 0;
    if (!attr_done) {
        cudaFuncSetAttribute(k_gemm_mma, cudaFuncAttributeMaxDynamicSharedMemorySize, SMEM_GEMM);
        attr_done = 1;
    }

    const int T = 256;
    const int scan_blocks = (N + 255) / 256;
    const int agg_blocks  = (N + 7) / 8;
    // CSR + norm precompute
    k_init <<<(N + T - 1) / T, T>>>(deg, cnt, N);
    k_hist <<<(E + T - 1) / T, T>>>(dst, ew, deg, cnt, E);
    k_dinv <<<(N + T - 1) / T, T>>>(deg, dinv, N);
    k_scan1<<<scan_blocks, 256>>>(cnt, off, bsum, N);
    k_scan2<<<1, 256>>>(bsum, scan_blocks);
    k_scan3<<<scan_blocks, 256>>>(bsum, off, head, N);
    k_fill <<<(E + T - 1) / T, T>>>(src, dst, ew, dinv, head, csrs, csrn, E);
    // weight panel conversion (pre-swizzled split-bf16)
    k_wconv<<<(F * 128 + 255) / 256, 256>>>(W1, wph,          wpl,          F);
    k_wconv<<<(H * 128 + 255) / 256, 256>>>(W2, wph + 81920,  wpl + 81920,  H);
    k_wconv<<<(H * 128 + 255) / 256, 256>>>(W3, wph + 122880, wpl + 122880, H);

    const int gemm_blocks = NPAD / 128;   // 391

    // layer 1
    k_gemm_mma<<<gemm_blocks, 256, SMEM_GEMM>>>(x, wph, wpl, hbuf, N, F);
    k_agg     <<<agg_blocks, 256>>>(hbuf, off, cnt, csrs, csrn, dinv, b1, agg, N);
    // layer 2
    k_gemm_mma<<<gemm_blocks, 256, SMEM_GEMM>>>(agg, wph + 81920, wpl + 81920, hbuf, NPAD, H);
    k_agg     <<<agg_blocks, 256>>>(hbuf, off, cnt, csrs, csrn, dinv, b2, agg, N);
    // layer 3
    k_gemm_mma<<<gemm_blocks, 256, SMEM_GEMM>>>(agg, wph + 122880, wpl + 122880, hbuf, NPAD, H);
    k_agg     <<<agg_blocks, 256>>>(hbuf, off, cnt, csrs, csrn, dinv, b3, agg, N);
    // head
    k_head<<<(N * 32 + T - 1) / T, T>>>(agg, fcw, fcb, out, N);
}

// round 7
// speedup vs baseline: 2.5770x; 1.5625x over previous
#include <cuda_runtime.h>
#include <cuda_bf16.h>
#include <math.h>

#define NMAX 50000
#define NPAD 50048          // multiple of 128 for unguarded MMA tiles
#define EMAX 800000
#define HD   128

// Scratch (device globals — no allocation allowed)
__device__ __align__(16) float g_deg[NMAX];
__device__ __align__(16) float g_dinv[NMAX];
__device__ __align__(16) int   g_cnt[NMAX];
__device__ __align__(16) int   g_off[NMAX];
__device__ __align__(16) int   g_head[NMAX];
__device__ __align__(16) int   g_bsum[256];
__device__ __align__(16) int   g_csr_src[EMAX];
__device__ __align__(16) float g_csr_nrm[EMAX];
__device__ __align__(16) float g_h[(size_t)NPAD * HD];    // GEMM output
__device__ __align__(16) float g_agg[(size_t)NPAD * HD];  // aggregation / layer output
// Pre-swizzled bf16 weight panels, [n=128][k] K-major, BK=32 chunks of 128x80B.
// L1 (K=256): [0, 81920); L2: [81920, 122880); L3: [122880, 163840)
__device__ __align__(16) unsigned char g_wp_hi[163840];
__device__ __align__(16) unsigned char g_wp_lo[163840];

// ---------------------------------------------------------------------------
__device__ __forceinline__ unsigned smem_u32(const void* p) {
    unsigned a;
    asm("{ .reg .u64 t; cvta.to.shared.u64 t, %1; cvt.u32.u64 %0, t; }" : "=r"(a) : "l"(p));
    return a;
}
__device__ __forceinline__ void ldsm4(unsigned* r, unsigned addr) {
    asm volatile("ldmatrix.sync.aligned.m8n8.x4.shared.b16 {%0,%1,%2,%3}, [%4];"
                 : "=r"(r[0]), "=r"(r[1]), "=r"(r[2]), "=r"(r[3]) : "r"(addr));
}
__device__ __forceinline__ void mma16816(float* c, const unsigned* a, unsigned b0, unsigned b1) {
    asm volatile("mma.sync.aligned.m16n8k16.row.col.f32.bf16.bf16.f32 "
                 "{%0,%1,%2,%3}, {%4,%5,%6,%7}, {%8,%9}, {%0,%1,%2,%3};"
                 : "+f"(c[0]), "+f"(c[1]), "+f"(c[2]), "+f"(c[3])
                 : "r"(a[0]), "r"(a[1]), "r"(a[2]), "r"(a[3]), "r"(b0), "r"(b1));
}
__device__ __forceinline__ void cpasync16(unsigned saddr, const void* gaddr) {
    asm volatile("cp.async.cg.shared.global [%0], [%1], 16;" :: "r"(saddr), "l"(gaddr));
}
#define CP_COMMIT() asm volatile("cp.async.commit_group;" ::: "memory")
#define CP_WAIT()   asm volatile("cp.async.wait_group 0;" ::: "memory")

// panel/tile byte offset inside a BK=32 chunk: row-major [row][k], stride 80B
__device__ __forceinline__ unsigned chunk_off(int row, int k) {
    return (unsigned)(row * 80 + k * 2);
}

// ---------------------------------------------------------------------------
__global__ void k_init(float* __restrict__ deg, int* __restrict__ cnt, int n) {
    int i = blockIdx.x * blockDim.x + threadIdx.x;
    if (i < n) { deg[i] = 1.0f; cnt[i] = 0; }   // self-loop weight 1
}

__global__ void k_hist(const int* __restrict__ dst, const float* __restrict__ ew,
                       float* __restrict__ deg, int* __restrict__ cnt, int E) {
    int e = blockIdx.x * blockDim.x + threadIdx.x;
    if (e < E) {
        int d = dst[e];
        atomicAdd(&deg[d], ew[e]);
        atomicAdd(&cnt[d], 1);
    }
}

__global__ void k_dinv(const float* __restrict__ deg, float* __restrict__ dinv, int n) {
    int i = blockIdx.x * blockDim.x + threadIdx.x;
    if (i < n) {
        float d = deg[i];
        dinv[i] = d > 0.0f ? rsqrtf(d) : 0.0f;
    }
}

__global__ void k_scan1(const int* __restrict__ cnt, int* __restrict__ off,
                        int* __restrict__ bsum, int n) {
    __shared__ int s[256];
    int i = blockIdx.x * 256 + threadIdx.x;
    int v = (i < n) ? cnt[i] : 0;
    s[threadIdx.x] = v;
    __syncthreads();
    for (int d = 1; d < 256; d <<= 1) {
        int t = (threadIdx.x >= d) ? s[threadIdx.x - d] : 0;
        __syncthreads();
        s[threadIdx.x] += t;
        __syncthreads();
    }
    if (i < n) off[i] = s[threadIdx.x] - v;
    if (threadIdx.x == 255) bsum[blockIdx.x] = s[255];
}

__global__ void k_scan2(int* __restrict__ bsum, int nb) {
    __shared__ int s[256];
    int t = threadIdx.x;
    int v = (t < nb) ? bsum[t] : 0;
    s[t] = v;
    __syncthreads();
    for (int d = 1; d < 256; d <<= 1) {
        int u = (t >= d) ? s[t - d] : 0;
        __syncthreads();
        s[t] += u;
        __syncthreads();
    }
    if (t < nb) bsum[t] = s[t] - v;
}

__global__ void k_scan3(const int* __restrict__ bsum, int* __restrict__ off,
                        int* __restrict__ head, int n) {
    int i = blockIdx.x * 256 + threadIdx.x;
    if (i < n) {
        int o = off[i] + bsum[blockIdx.x];
        off[i] = o;
        head[i] = o;
    }
}

// scatter edges into CSR order with normalized weight dinv[src]*ew
__global__ void k_fill(const int* __restrict__ src, const int* __restrict__ dst,
                       const float* __restrict__ ew, const float* __restrict__ dinv,
                       int* __restrict__ head, int* __restrict__ csr_src,
                       float* __restrict__ csr_w, int E) {
    int e = blockIdx.x * blockDim.x + threadIdx.x;
    if (e < E) {
        int s = src[e], d = dst[e];
        int p = atomicAdd(&head[d], 1);
        csr_src[p] = s;
        csr_w[p] = dinv[s] * ew[e];
    }
}

// ---------------------------------------------------------------------------
// Convert W[K][128] fp32 -> split-bf16 panels [n][k] K-major, BK=32 chunked, 80B row stride
__global__ void k_wconv(const float* __restrict__ W, unsigned char* __restrict__ hi,
                        unsigned char* __restrict__ lo, int K) {
    int e = blockIdx.x * 256 + threadIdx.x;
    if (e >= K * 128) return;
    int k = e >> 7, n = e & 127;
    float x = W[e];
    __nv_bfloat16 h = __float2bfloat16(x);
    __nv_bfloat16 l = __float2bfloat16(x - __bfloat162float(h));
    unsigned so = (unsigned)(k >> 5) * 10240u + chunk_off(n, k & 31);
    *(__nv_bfloat16*)(hi + so) = h;
    *(__nv_bfloat16*)(lo + so) = l;
}

// ---------------------------------------------------------------------------
// mma.sync bf16-split GEMM: C[NPAD,128] = A[*,K] @ W[K,128].
// CTA tile 128x128, BK=32 double-buffered, 256 threads (8 warps, 2x4), warp tile 64x32.
// Stage layout (per buffer, 40960 B): A_hi[128x80B] | A_lo | B_hi | B_lo
__global__ __launch_bounds__(256) void k_gemm_mma(
    const float* __restrict__ A, const unsigned char* __restrict__ wp_hi,
    const unsigned char* __restrict__ wp_lo, float* __restrict__ C, int Mreal, int K) {
    extern __shared__ __align__(16) unsigned char smem[];
    const unsigned sbase = smem_u32(smem);

    const int tid  = threadIdx.x;
    const int wid  = tid >> 5;
    const int lane = tid & 31;
    const int wm   = wid >> 2;      // 0..1
    const int wn   = wid & 3;       // 0..3
    const int m0   = blockIdx.x * 128;

    float acc[4][4][4];
#pragma unroll
    for (int i = 0; i < 4; i++)
#pragma unroll
        for (int j = 0; j < 4; j++)
#pragma unroll
            for (int r = 0; r < 4; r++) acc[i][j][r] = 0.0f;

    const int nst = K >> 5;

    auto issueB = [&](int buf, int kc) {
        const unsigned bh = sbase + buf * 40960 + 20480;
        const unsigned bl = bh + 10240;
        const unsigned char* gh = wp_hi + (size_t)kc * 10240;
        const unsigned char* gl = wp_lo + (size_t)kc * 10240;
        for (int i = tid; i < 640; i += 256) {
            cpasync16(bh + i * 16, gh + i * 16);
            cpasync16(bl + i * 16, gl + i * 16);
        }
        CP_COMMIT();
    };
    auto loadAregs = [&](int kc, float4* v) {
#pragma unroll
        for (int it = 0; it < 4; it++) {
            int f4 = it * 256 + tid;
            int row = f4 >> 3, kl = (f4 & 7) << 2;
            int gr = m0 + row;
            v[it] = make_float4(0.f, 0.f, 0.f, 0.f);
            if (gr < Mreal)
                v[it] = *(const float4*)(A + (size_t)gr * K + (kc << 5) + kl);
        }
    };
    auto storeA = [&](int buf, const float4* v) {
        unsigned char* bp = smem + buf * 40960;
#pragma unroll
        for (int it = 0; it < 4; it++) {
            int f4 = it * 256 + tid;
            int row = f4 >> 3, kl = (f4 & 7) << 2;
            float4 x = v[it];
            __nv_bfloat16 hx = __float2bfloat16(x.x), hy = __float2bfloat16(x.y);
            __nv_bfloat16 hz = __float2bfloat16(x.z), hw = __float2bfloat16(x.w);
            __nv_bfloat16 lx = __float2bfloat16(x.x - __bfloat162float(hx));
            __nv_bfloat16 ly = __float2bfloat16(x.y - __bfloat162float(hy));
            __nv_bfloat16 lz = __float2bfloat16(x.z - __bfloat162float(hz));
            __nv_bfloat16 lw = __float2bfloat16(x.w - __bfloat162float(hw));
            unsigned h0 = (unsigned)__bfloat16_as_ushort(hx) | ((unsigned)__bfloat16_as_ushort(hy) << 16);
            unsigned h1 = (unsigned)__bfloat16_as_ushort(hz) | ((unsigned)__bfloat16_as_ushort(hw) << 16);
            unsigned l0 = (unsigned)__bfloat16_as_ushort(lx) | ((unsigned)__bfloat16_as_ushort(ly) << 16);
            unsigned l1 = (unsigned)__bfloat16_as_ushort(lz) | ((unsigned)__bfloat16_as_ushort(lw) << 16);
            unsigned off = chunk_off(row, kl);
            *(uint2*)(bp + off)         = make_uint2(h0, h1);
            *(uint2*)(bp + 10240 + off) = make_uint2(l0, l1);
        }
    };
    auto compute = [&](int buf) {
        const unsigned aH = sbase + buf * 40960;
        const unsigned aL = aH + 10240;
        const unsigned bH = aH + 20480;
        const unsigned bL = aH + 30720;
        const int rsel = lane & 15;
        const unsigned koff16 = ((lane >> 4) << 4);   // 0 or 16 bytes (k +8 elements)
#pragma unroll
        for (int s = 0; s < 2; s++) {
            const unsigned kb = (unsigned)(s * 32) + koff16;
            unsigned ah[4][4], al[4][4], bh[2][4], bl[2][4];
#pragma unroll
            for (int mi = 0; mi < 4; mi++) {
                unsigned ro = chunk_off(wm * 64 + mi * 16 + rsel, 0) + kb;
                ldsm4(ah[mi], aH + ro);
                ldsm4(al[mi], aL + ro);
            }
#pragma unroll
            for (int g = 0; g < 2; g++) {
                unsigned ro = chunk_off(wn * 32 + g * 16 + rsel, 0) + kb;
                ldsm4(bh[g], bH + ro);
                ldsm4(bl[g], bL + ro);
            }
#pragma unroll
            for (int mi = 0; mi < 4; mi++)
#pragma unroll
                for (int nj = 0; nj < 4; nj++) {
                    int g = nj >> 1, o = nj & 1;
                    mma16816(acc[mi][nj], ah[mi], bh[g][o], bh[g][o + 2]);
                    mma16816(acc[mi][nj], ah[mi], bl[g][o], bl[g][o + 2]);
                    mma16816(acc[mi][nj], al[mi], bh[g][o], bh[g][o + 2]);
                }
        }
    };

    // ---- pipeline ----
    float4 stage[4];
    issueB(0, 0);
    loadAregs(0, stage);
    storeA(0, stage);
    CP_WAIT();
    __syncthreads();

    for (int kc = 0; kc < nst; kc++) {
        const int cur = kc & 1, nxt = cur ^ 1;
        const bool more = (kc + 1 < nst);
        if (more) {
            issueB(nxt, kc + 1);
            loadAregs(kc + 1, stage);
        }
        compute(cur);
        if (more) {
            storeA(nxt, stage);
            CP_WAIT();
        }
        __syncthreads();
    }

    // ---- epilogue: unguarded (C padded to NPAD rows) ----
#pragma unroll
    for (int mi = 0; mi < 4; mi++) {
        int gm = m0 + wm * 64 + mi * 16 + (lane >> 2);
#pragma unroll
        for (int nj = 0; nj < 4; nj++) {
            int col = wn * 32 + nj * 8 + (lane & 3) * 2;
            *(float2*)(C + (size_t)gm * 128 + col)       = make_float2(acc[mi][nj][0], acc[mi][nj][1]);
            *(float2*)(C + (size_t)(gm + 8) * 128 + col) = make_float2(acc[mi][nj][2], acc[mi][nj][3]);
        }
    }
}

// ---------------------------------------------------------------------------
// Fused per-node aggregation: one warp per dst node.
__global__ void k_agg(const float* __restrict__ h, const int* __restrict__ off,
                      const int* __restrict__ cnt, const int* __restrict__ csr_src,
                      const float* __restrict__ csr_nrm, const float* __restrict__ dinv,
                      const float* __restrict__ bias, float* __restrict__ outp, int n) {
    int node = blockIdx.x * (blockDim.x >> 5) + (threadIdx.x >> 5);
    int lane = threadIdx.x & 31;
    if (node >= n) return;

    const float di = dinv[node];
    float4 acc = *(const float4*)(h + (size_t)node * HD + lane * 4);
    acc.x *= di; acc.y *= di; acc.z *= di; acc.w *= di;

    const int m    = cnt[node];
    const int base = off[node];
    int j = 0;
    for (; j + 4 <= m; j += 4) {
        int s0 = __ldg(csr_src + base + j + 0);
        int s1 = __ldg(csr_src + base + j + 1);
        int s2 = __ldg(csr_src + base + j + 2);
        int s3 = __ldg(csr_src + base + j + 3);
        float w0 = __ldg(csr_nrm + base + j + 0);
        float w1 = __ldg(csr_nrm + base + j + 1);
        float w2 = __ldg(csr_nrm + base + j + 2);
        float w3 = __ldg(csr_nrm + base + j + 3);
        float4 v0 = *(const float4*)(h + (size_t)s0 * HD + lane * 4);
        float4 v1 = *(const float4*)(h + (size_t)s1 * HD + lane * 4);
        float4 v2 = *(const float4*)(h + (size_t)s2 * HD + lane * 4);
        float4 v3 = *(const float4*)(h + (size_t)s3 * HD + lane * 4);
        acc.x = fmaf(w0, v0.x, acc.x); acc.y = fmaf(w0, v0.y, acc.y);
        acc.z = fmaf(w0, v0.z, acc.z); acc.w = fmaf(w0, v0.w, acc.w);
        acc.x = fmaf(w1, v1.x, acc.x); acc.y = fmaf(w1, v1.y, acc.y);
        acc.z = fmaf(w1, v1.z, acc.z); acc.w = fmaf(w1, v1.w, acc.w);
        acc.x = fmaf(w2, v2.x, acc.x); acc.y = fmaf(w2, v2.y, acc.y);
        acc.z = fmaf(w2, v2.z, acc.z); acc.w = fmaf(w2, v2.w, acc.w);
        acc.x = fmaf(w3, v3.x, acc.x); acc.y = fmaf(w3, v3.y, acc.y);
        acc.z = fmaf(w3, v3.z, acc.z); acc.w = fmaf(w3, v3.w, acc.w);
    }
    for (; j < m; j++) {
        int sj = __ldg(csr_src + base + j);
        float wj = __ldg(csr_nrm + base + j);
        float4 v = *(const float4*)(h + (size_t)sj * HD + lane * 4);
        acc.x = fmaf(wj, v.x, acc.x); acc.y = fmaf(wj, v.y, acc.y);
        acc.z = fmaf(wj, v.z, acc.z); acc.w = fmaf(wj, v.w, acc.w);
    }

    float4 bb = ((const float4*)bias)[lane];
    acc.x = fmaxf(fmaf(di, acc.x, bb.x), 0.0f);
    acc.y = fmaxf(fmaf(di, acc.y, bb.y), 0.0f);
    acc.z = fmaxf(fmaf(di, acc.z, bb.z), 0.0f);
    acc.w = fmaxf(fmaf(di, acc.w, bb.w), 0.0f);
    *(float4*)(outp + (size_t)node * HD + lane * 4) = acc;
}

// ---------------------------------------------------------------------------
__global__ void k_head(const float* __restrict__ h, const float* __restrict__ fcw,
                       const float* __restrict__ fcb, float* __restrict__ out, int n) {
    __shared__ float sw[HD * 10];
    __shared__ float sb[10];
    for (int i = threadIdx.x; i < HD * 10; i += blockDim.x) sw[i] = fcw[i];
    if (threadIdx.x < 10) sb[threadIdx.x] = fcb[threadIdx.x];
    __syncthreads();
    int node = (blockIdx.x * blockDim.x + threadIdx.x) >> 5;
    int lane = threadIdx.x & 31;
    if (node >= n) return;
    float4 hv = *(const float4*)(h + (size_t)node * HD + lane * 4);
    int k = lane * 4;
    float part[10];
#pragma unroll
    for (int c = 0; c < 10; c++) {
        part[c] = hv.x * sw[(k + 0) * 10 + c] + hv.y * sw[(k + 1) * 10 + c]
                + hv.z * sw[(k + 2) * 10 + c] + hv.w * sw[(k + 3) * 10 + c];
    }
#pragma unroll
    for (int off = 16; off; off >>= 1)
#pragma unroll
        for (int c = 0; c < 10; c++)
            part[c] += __shfl_xor_sync(0xffffffffu, part[c], off);
    if (lane == 0) {
        float m = -1e30f;
#pragma unroll
        for (int c = 0; c < 10; c++) { part[c] += sb[c]; m = fmaxf(m, part[c]); }
        float s = 0.0f;
#pragma unroll
        for (int c = 0; c < 10; c++) { part[c] = expf(part[c] - m); s += part[c]; }
        float inv = 1.0f / s;
#pragma unroll
        for (int c = 0; c < 10; c++) out[(size_t)node * 10 + c] = part[c] * inv;
    }
}

// ---------------------------------------------------------------------------
extern "C" void kernel_launch(void* const* d_in, const int* in_sizes, int n_in,
                              void* d_out, int out_size) {
    const float* x   = (const float*)d_in[0];
    const int*   ei  = (const int*)d_in[1];
    const float* ew  = (const float*)d_in[2];
    const float* W1  = (const float*)d_in[3];
    const float* b1  = (const float*)d_in[4];
    const float* W2  = (const float*)d_in[5];
    const float* b2  = (const float*)d_in[6];
    const float* W3  = (const float*)d_in[7];
    const float* b3  = (const float*)d_in[8];
    const float* fcw = (const float*)d_in[9];
    const float* fcb = (const float*)d_in[10];
    float* out = (float*)d_out;

    const int H = in_sizes[4];              // 128
    const int F = in_sizes[3] / H;          // 256
    const int N = in_sizes[0] / F;          // 50000
    const int E = in_sizes[2];              // 800000
    (void)n_in; (void)out_size;

    const int* src = ei;
    const int* dst = ei + E;

    float* deg;  cudaGetSymbolAddress((void**)&deg,  g_deg);
    float* dinv; cudaGetSymbolAddress((void**)&dinv, g_dinv);
    int*   cnt;  cudaGetSymbolAddress((void**)&cnt,  g_cnt);
    int*   off;  cudaGetSymbolAddress((void**)&off,  g_off);
    int*   head; cudaGetSymbolAddress((void**)&head, g_head);
    int*   bsum; cudaGetSymbolAddress((void**)&bsum, g_bsum);
    int*   csrs; cudaGetSymbolAddress((void**)&csrs, g_csr_src);
    float* csrn; cudaGetSymbolAddress((void**)&csrn, g_csr_nrm);
    float* hbuf; cudaGetSymbolAddress((void**)&hbuf, g_h);
    float* agg;  cudaGetSymbolAddress((void**)&agg,  g_agg);
    unsigned char* wph; cudaGetSymbolAddress((void**)&wph, g_wp_hi);
    unsigned char* wpl; cudaGetSymbolAddress((void**)&wpl, g_wp_lo);

    const int SMEM_GEMM = 81920;
    static cudaStream_t s2 = 0;
    static cudaEvent_t evRoot = 0, evPre = 0;
    if (!s2) {
        cudaFuncSetAttribute(k_gemm_mma, cudaFuncAttributeMaxDynamicSharedMemorySize, SMEM_GEMM);
        cudaStreamCreateWithFlags(&s2, cudaStreamNonBlocking);
        cudaEventCreateWithFlags(&evRoot, cudaEventDisableTiming);
        cudaEventCreateWithFlags(&evPre, cudaEventDisableTiming);
    }

    const int T = 256;
    const int scan_blocks = (N + 255) / 256;
    const int agg_blocks  = (N + 7) / 8;
    const int gemm_blocks = NPAD / 128;   // 391

    // ---- fork: CSR precompute on side stream, overlapped with wconv+GEMM1 ----
    cudaEventRecord(evRoot, 0);
    cudaStreamWaitEvent(s2, evRoot, 0);

    k_init <<<(N + T - 1) / T, T, 0, s2>>>(deg, cnt, N);
    k_hist <<<(E + T - 1) / T, T, 0, s2>>>(dst, ew, deg, cnt, E);
    k_dinv <<<(N + T - 1) / T, T, 0, s2>>>(deg, dinv, N);
    k_scan1<<<scan_blocks, 256, 0, s2>>>(cnt, off, bsum, N);
    k_scan2<<<1, 256, 0, s2>>>(bsum, scan_blocks);
    k_scan3<<<scan_blocks, 256, 0, s2>>>(bsum, off, head, N);
    k_fill <<<(E + T - 1) / T, T, 0, s2>>>(src, dst, ew, dinv, head, csrs, csrn, E);
    cudaEventRecord(evPre, s2);

    // main stream: weight conversion + layer-1 GEMM (independent of CSR)
    k_wconv<<<(F * 128 + 255) / 256, 256>>>(W1, wph,          wpl,          F);
    k_wconv<<<(H * 128 + 255) / 256, 256>>>(W2, wph + 81920,  wpl + 81920,  H);
    k_wconv<<<(H * 128 + 255) / 256, 256>>>(W3, wph + 122880, wpl + 122880, H);
    k_gemm_mma<<<gemm_blocks, 256, SMEM_GEMM>>>(x, wph, wpl, hbuf, N, F);

    // ---- join: aggregation needs the CSR ----
    cudaStreamWaitEvent(0, evPre, 0);

    // layer 1
    k_agg<<<agg_blocks, 256>>>(hbuf, off, cnt, csrs, csrn, dinv, b1, agg, N);
    // layer 2
    k_gemm_mma<<<gemm_blocks, 256, SMEM_GEMM>>>(agg, wph + 81920, wpl + 81920, hbuf, NPAD, H);
    k_agg<<<agg_blocks, 256>>>(hbuf, off, cnt, csrs, csrn, dinv, b2, agg, N);
    // layer 3
    k_gemm_mma<<<gemm_blocks, 256, SMEM_GEMM>>>(agg, wph + 122880, wpl + 122880, hbuf, NPAD, H);
    k_agg<<<agg_blocks, 256>>>(hbuf, off, cnt, csrs, csrn, dinv, b3, agg, N);
    // head
    k_head<<<(N * 32 + T - 1) / T, T>>>(agg, fcw, fcb, out, N);
}